// round 12
// baseline (speedup 1.0000x reference)
#include <cuda_runtime.h>
#include <cuda_bf16.h>
#include <cuda_fp16.h>
#include <cstdint>

static constexpr int B_ = 128, P_ = 196, ENC_ = 2048, A_ = 512, H_ = 512;
static constexpr int V_ = 20000, T_ = 20, H3_ = 1536, EX_ = 2560;
static constexpr long CAP_OFF   = (long)B_ * T_ * V_;   // 51,200,000
static constexpr long ALPHA_OFF = CAP_OFF + B_;         // 51,200,128
static constexpr int  M1_ = B_ * P_;                    // 25088
static constexpr int  MH_ = (T_ - 1) * B_;              // 2432

// ---------------- device scratch ------------------------------------------
__device__ __align__(16) __half g_img16[(size_t)M1_ * ENC_];
__device__ __align__(16) __half g_att1h[(size_t)M1_ * A_];
__device__ __align__(16) __half g_WeT16h[A_ * ENC_], g_WeT16l[A_ * ENC_];
__device__ __align__(16) __half g_Bcat16h[2048 * 512], g_Bcat16l[2048 * 512];
__device__ __align__(16) float  g_bias_cat[2048];
__device__ __align__(16) __half g_Wih16h[H3_ * EX_], g_Wih16l[H3_ * EX_];
__device__ __align__(16) __half g_Wo16h[(size_t)V_ * H_], g_Wo16l[(size_t)V_ * H_];
__device__ __align__(16) __half g_Xemb16[MH_ * 512];
__device__ __align__(16) float  g_gi_emb[(size_t)MH_ * H3_];
__device__ __align__(16) float  g_ag[2][B_ * 2048];     // split-K partials: att2|gh
__device__ __align__(16) float  g_gi4[4][B_ * H3_];     // split-K partials: gi_ctx
__device__ __align__(16) float  g_alpha[B_ * P_];
__device__ __align__(16) __half g_x16[B_ * ENC_];       // ctx fp16
__device__ __align__(16) float  g_h[B_ * H_];
__device__ __align__(16) __half g_h16[B_ * H_];
__device__ __align__(16) __half g_hall16[MH_ * H_];

// ---------------- helpers --------------------------------------------------
__device__ __forceinline__ uint32_t s2u(const void* p) {
    return (uint32_t)__cvta_generic_to_shared(p);
}
__device__ __forceinline__ void ldsm4(uint32_t r[4], uint32_t a) {
    asm volatile("ldmatrix.sync.aligned.m8n8.x4.shared.b16 {%0,%1,%2,%3},[%4];"
                 : "=r"(r[0]), "=r"(r[1]), "=r"(r[2]), "=r"(r[3]) : "r"(a));
}
__device__ __forceinline__ void mma16816h(float c[4], const uint32_t a[4], const uint32_t b[2]) {
    asm volatile(
        "mma.sync.aligned.m16n8k16.row.col.f32.f16.f16.f32 "
        "{%0,%1,%2,%3},{%4,%5,%6,%7},{%8,%9},{%0,%1,%2,%3};"
        : "+f"(c[0]), "+f"(c[1]), "+f"(c[2]), "+f"(c[3])
        : "r"(a[0]), "r"(a[1]), "r"(a[2]), "r"(a[3]), "r"(b[0]), "r"(b[1]));
}
#define CP16(d, s) asm volatile("cp.async.cg.shared.global [%0],[%1],16;\n" :: "r"(d), "l"(s))
#define CPCOMMIT() asm volatile("cp.async.commit_group;\n")

__device__ __forceinline__ void split2h(float v, __half& h, __half& l) {
    h = __float2half_rn(v);
    l = __float2half_rn(v - __half2float(h));
}

// ---------------- fp16 2-MMA GEMM: C = A16 @ (Bh+Bl)^T (+bias) --------------
// A [M,K] fp16 row-major. B [N,K] fp16 hi/lo row-major.
// 256 thr, tile 128x64x32, cp.async double-buffered, 80B-padded smem rows.
static constexpr int HSA = 128 * 40;
static constexpr int HSB = 64 * 40;
static constexpr int HSTG = HSA + 2 * HSB;       // 10240 halves
static constexpr int GEMMH_SMEM = 2 * HSTG * 2;  // 40960 B

__global__ __launch_bounds__(256) void gemm2h(
    const __half* __restrict__ Ag, int lda,
    const __half* __restrict__ Bgh, const __half* __restrict__ Bgl, int ldb,
    const float* __restrict__ bias, void* __restrict__ Cbase,
    long tile_stride, long row_stride, long part_stride,
    int N, int Ktot, int out_half, int swap_xy)
{
    extern __shared__ __align__(16) __half smh[];
    const int tid = threadIdx.x, lane = tid & 31, warp = tid >> 5;
    const int wm = warp >> 1, wn = warp & 1;
    const int bx = swap_xy ? blockIdx.y : blockIdx.x;
    const int by = swap_xy ? blockIdx.x : blockIdx.y;
    const int n0 = bx * 64, m0 = by * 128;
    const int ks = blockIdx.z;
    const int Ksub = Ktot / gridDim.z, kbase = ks * Ksub;

    float acc[2][4][4];
#pragma unroll
    for (int i = 0; i < 2; i++)
#pragma unroll
        for (int j = 0; j < 4; j++)
#pragma unroll
            for (int k = 0; k < 4; k++) acc[i][j][k] = 0.f;

    auto load_stage = [&](int st, int k0) {
        __half* As  = smh + st * HSTG;
        __half* Bsh = As + HSA;
        __half* Bsl = Bsh + HSB;
#pragma unroll
        for (int it = 0; it < 2; it++) {
            int idx = tid + it * 256, r = idx >> 2, ch = idx & 3;
            CP16(s2u(As + r * 40 + ch * 8), Ag + (size_t)(m0 + r) * lda + k0 + ch * 8);
        }
        {
            int r = tid >> 2, ch = tid & 3;
            int rr = (n0 + r < N) ? (n0 + r) : (N - 1);
            size_t go = (size_t)rr * ldb + k0 + ch * 8;
            CP16(s2u(Bsh + r * 40 + ch * 8), Bgh + go);
            CP16(s2u(Bsl + r * 40 + ch * 8), Bgl + go);
        }
        CPCOMMIT();
    };

    const int nk = Ksub / 32;
    load_stage(0, kbase);
    for (int i = 0; i < nk; i++) {
        if (i + 1 < nk) {
            load_stage((i + 1) & 1, kbase + (i + 1) * 32);
            asm volatile("cp.async.wait_group 1;\n");
        } else {
            asm volatile("cp.async.wait_group 0;\n");
        }
        __syncthreads();
        __half* As  = smh + (i & 1) * HSTG;
        __half* Bsh = As + HSA;
        __half* Bsl = Bsh + HSB;
#pragma unroll
        for (int kk = 0; kk < 32; kk += 16) {
            uint32_t ah[2][4], bh[4][2], bl[4][2];
#pragma unroll
            for (int mt = 0; mt < 2; mt++) {
                int off = (wm * 32 + mt * 16 + (lane & 15)) * 40 + kk + ((lane >> 4) << 3);
                ldsm4(ah[mt], s2u(As + off));
            }
#pragma unroll
            for (int ng = 0; ng < 2; ng++) {
                int off = (wn * 32 + ng * 16 + (lane & 15)) * 40 + kk + ((lane >> 4) << 3);
                uint32_t t4[4];
                ldsm4(t4, s2u(Bsh + off));
                bh[ng * 2][0] = t4[0]; bh[ng * 2][1] = t4[2];
                bh[ng * 2 + 1][0] = t4[1]; bh[ng * 2 + 1][1] = t4[3];
                ldsm4(t4, s2u(Bsl + off));
                bl[ng * 2][0] = t4[0]; bl[ng * 2][1] = t4[2];
                bl[ng * 2 + 1][0] = t4[1]; bl[ng * 2 + 1][1] = t4[3];
            }
#pragma unroll
            for (int mt = 0; mt < 2; mt++)
#pragma unroll
                for (int nt = 0; nt < 4; nt++) {
                    mma16816h(acc[mt][nt], ah[mt], bh[nt]);
                    mma16816h(acc[mt][nt], ah[mt], bl[nt]);
                }
        }
        __syncthreads();
    }

    const bool addb = (bias != nullptr) && (ks == 0);
    if (!out_half) {
        float* Cp = (float*)Cbase + (long)by * tile_stride + (long)ks * part_stride;
#pragma unroll
        for (int mt = 0; mt < 2; mt++) {
            int r = wm * 32 + mt * 16 + (lane >> 2);
#pragma unroll
            for (int nt = 0; nt < 4; nt++) {
                int col = n0 + wn * 32 + nt * 8 + (lane & 3) * 2;
                if (col < N) {
                    float bb = addb ? bias[col] : 0.f;
                    Cp[(long)r * row_stride + col]       = acc[mt][nt][0] + bb;
                    Cp[(long)(r + 8) * row_stride + col] = acc[mt][nt][2] + bb;
                }
                if (col + 1 < N) {
                    float bb = addb ? bias[col + 1] : 0.f;
                    Cp[(long)r * row_stride + col + 1]       = acc[mt][nt][1] + bb;
                    Cp[(long)(r + 8) * row_stride + col + 1] = acc[mt][nt][3] + bb;
                }
            }
        }
    } else {
        __half* Cp = (__half*)Cbase + (long)by * tile_stride + (long)ks * part_stride;
#pragma unroll
        for (int mt = 0; mt < 2; mt++) {
            int r = wm * 32 + mt * 16 + (lane >> 2);
#pragma unroll
            for (int nt = 0; nt < 4; nt++) {
                int col = n0 + wn * 32 + nt * 8 + (lane & 3) * 2;
                float b0 = addb ? bias[col] : 0.f;
                float b1 = addb ? bias[col + 1] : 0.f;
                __half2 w0 = {__float2half_rn(acc[mt][nt][0] + b0), __float2half_rn(acc[mt][nt][1] + b1)};
                __half2 w1 = {__float2half_rn(acc[mt][nt][2] + b0), __float2half_rn(acc[mt][nt][3] + b1)};
                *(__half2*)(Cp + (long)r * row_stride + col)       = w0;
                *(__half2*)(Cp + (long)(r + 8) * row_stride + col) = w1;
            }
        }
    }
}

// ---------------- prep kernels ----------------------------------------------
__global__ void prep_img_k(const float* __restrict__ src, long n4)
{
    long i = (long)blockIdx.x * 256 + threadIdx.x;
    if (i >= n4) return;
    float4 v = ((const float4*)src)[i];
    ((__half2*)(g_img16 + 4 * i))[0] = {__float2half_rn(v.x), __float2half_rn(v.y)};
    ((__half2*)(g_img16 + 4 * i))[1] = {__float2half_rn(v.z), __float2half_rn(v.w)};
}

__global__ void split4h_k(const float* __restrict__ src, __half* __restrict__ dh,
                          __half* __restrict__ dl, long n4)
{
    long i = (long)blockIdx.x * 256 + threadIdx.x;
    if (i >= n4) return;
    float4 v = ((const float4*)src)[i];
    __half h0, h1, h2, h3, l0, l1, l2, l3;
    split2h(v.x, h0, l0); split2h(v.y, h1, l1); split2h(v.z, h2, l2); split2h(v.w, h3, l3);
    ((__half2*)(dh + 4 * i))[0] = {h0, h1};
    ((__half2*)(dh + 4 * i))[1] = {h2, h3};
    ((__half2*)(dl + 4 * i))[0] = {l0, l1};
    ((__half2*)(dl + 4 * i))[1] = {l2, l3};
}

__global__ void transpose_split_h(const float* __restrict__ src, __half* __restrict__ dh,
                                  __half* __restrict__ dl, int R, int C)
{
    __shared__ float tile[32][33];
    int c0 = blockIdx.x * 32, r0 = blockIdx.y * 32;
    int tx = threadIdx.x, ty = threadIdx.y;  // (32, 8)
#pragma unroll
    for (int i = 0; i < 4; i++) {
        int r = r0 + ty + i * 8;
        if (r < R && c0 + tx < C) tile[ty + i * 8][tx] = src[(size_t)r * C + c0 + tx];
    }
    __syncthreads();
#pragma unroll
    for (int i = 0; i < 4; i++) {
        int orow = c0 + ty + i * 8, ocol = r0 + tx;
        if (orow < C && ocol < R) {
            __half h, l;
            split2h(tile[tx][ty + i * 8], h, l);
            dh[(size_t)orow * R + ocol] = h;
            dl[(size_t)orow * R + ocol] = l;
        }
    }
}

__global__ void emb_gather_k(const float* __restrict__ emb, const int* __restrict__ cap)
{
    const int b = blockIdx.x, tt = blockIdx.y;   // tt = t-1, 0..18
    const int w = cap[b * 20 + tt];
    __half* dst = g_Xemb16 + (size_t)(tt * 128 + b) * 512;
    const float* s = emb + (size_t)w * 512;
    for (int i = threadIdx.x; i < 512; i += 128) dst[i] = __float2half_rn(s[i]);
}

__global__ void biascat_k(const float* __restrict__ bd, const float* __restrict__ bhh)
{
    int i = blockIdx.x * 256 + threadIdx.x;
    if (i < 512) g_bias_cat[i] = bd[i];
    else if (i < 2048) g_bias_cat[i] = bhh[i - 512];
}

__global__ void zero_h_k()
{
    int i = blockIdx.x * 256 + threadIdx.x;
    if (i < B_ * H_) { g_h[i] = 0.f; g_h16[i] = __float2half_rn(0.f); }
}

__global__ void init_out_k(float* __restrict__ out, const int* __restrict__ caplen)
{
    long i = (long)blockIdx.x * 256 + threadIdx.x;
    const long n0 = (long)B_ * V_;
    if (i < n0) {
        long b = i / V_, v2 = i % V_;
        out[b * 400000 + v2] = (v2 == 1) ? 1.f : 0.f;
    } else if (i < n0 + B_ * P_) {
        long j = i - n0, b = j / P_, p = j % P_;
        out[ALPHA_OFF + b * (T_ * P_) + p] = 0.f;
    } else if (i < n0 + B_ * P_ + B_) {
        int b = (int)(i - n0 - B_ * P_);
        out[CAP_OFF + b] = (float)caplen[b];
    }
}

// ---------------- per-step kernels ------------------------------------------
__global__ __launch_bounds__(256) void score_softmax_k(
    const float* __restrict__ wf, const float* __restrict__ bfp,
    float* __restrict__ out, int t)
{
    __shared__ float att2s[512], wfs[512], sc[200], red[256];
    const int b = blockIdx.x, tid = threadIdx.x, lane = tid & 31, warp = tid >> 5;
    for (int i = tid; i < 512; i += 256) {
        att2s[i] = g_ag[0][b * 2048 + i] + g_ag[1][b * 2048 + i];
        wfs[i] = wf[i];
    }
    __syncthreads();
    const float bfv = bfp[0];
    for (int p = warp; p < 196; p += 8) {
        const __half2* row = (const __half2*)(g_att1h + ((size_t)b * 196 + p) * 512);
        float s = 0.f;
#pragma unroll
        for (int i = 0; i < 8; i++) {
            int c = lane + i * 32;
            float2 vf = __half22float2(row[c]);
            s += fmaxf(vf.x + att2s[2 * c], 0.f) * wfs[2 * c]
               + fmaxf(vf.y + att2s[2 * c + 1], 0.f) * wfs[2 * c + 1];
        }
#pragma unroll
        for (int o = 16; o; o >>= 1) s += __shfl_xor_sync(0xffffffffu, s, o);
        if (lane == 0) sc[p] = s + bfv;
    }
    __syncthreads();
    float v = (tid < 196) ? sc[tid] : -1e30f;
    red[tid] = v; __syncthreads();
    for (int o = 128; o; o >>= 1) { if (tid < o) red[tid] = fmaxf(red[tid], red[tid + o]); __syncthreads(); }
    float m = red[0]; __syncthreads();
    float e = (tid < 196) ? __expf(sc[tid] - m) : 0.f;
    red[tid] = e; __syncthreads();
    for (int o = 128; o; o >>= 1) { if (tid < o) red[tid] += red[tid + o]; __syncthreads(); }
    float inv = 1.f / red[0];
    if (tid < 196) {
        float a = e * inv;
        g_alpha[b * 196 + tid] = a;
        out[ALPHA_OFF + ((size_t)b * 20 + t) * 196 + tid] = a;
    }
}

// ctx weighted sum (fp16 img, uint4 loads, unroll 4) -> x16 [128, 2048] fp16
// 256 uint4 columns per row; grid (2, 128) x 128 threads.
__global__ void ctx_k()
{
    __shared__ float al[196];
    const int b = blockIdx.y, tid = threadIdx.x;
    for (int i = tid; i < 196; i += 128) al[i] = g_alpha[b * 196 + i];
    __syncthreads();
    const uint4* ip = (const uint4*)(g_img16 + (size_t)b * 196 * 2048);
    const int c0 = blockIdx.x * 128 + tid;   // uint4 column, 0..255
    float acc[8] = {0.f};
#pragma unroll 4
    for (int p = 0; p < 196; p++) {
        uint4 v = ip[(size_t)p * 256 + c0];
        float a = al[p];
        float2 f;
        f = __half22float2(*(__half2*)&v.x); acc[0] += a * f.x; acc[1] += a * f.y;
        f = __half22float2(*(__half2*)&v.y); acc[2] += a * f.x; acc[3] += a * f.y;
        f = __half22float2(*(__half2*)&v.z); acc[4] += a * f.x; acc[5] += a * f.y;
        f = __half22float2(*(__half2*)&v.w); acc[6] += a * f.x; acc[7] += a * f.y;
    }
    uint4 o;
    *(__half2*)&o.x = {__float2half_rn(acc[0]), __float2half_rn(acc[1])};
    *(__half2*)&o.y = {__float2half_rn(acc[2]), __float2half_rn(acc[3])};
    *(__half2*)&o.z = {__float2half_rn(acc[4]), __float2half_rn(acc[5])};
    *(__half2*)&o.w = {__float2half_rn(acc[6]), __float2half_rn(acc[7])};
    ((uint4*)(g_x16 + b * 2048))[c0] = o;
}

__global__ void gates_k(int t)
{
    int idx = blockIdx.x * 256 + threadIdx.x;
    if (idx >= B_ * H_) return;
    int b = idx >> 9, j = idx & 511;
    const float* ge = g_gi_emb + (size_t)((t - 1) * 128 + b) * 1536;
    int base = b * 1536;
    float gir = ge[j], giz = ge[512 + j], gin = ge[1024 + j];
#pragma unroll
    for (int s = 0; s < 4; s++) {
        gir += g_gi4[s][base + j];
        giz += g_gi4[s][base + 512 + j];
        gin += g_gi4[s][base + 1024 + j];
    }
    int gb = b * 2048;
    float ghr = g_ag[0][gb + 512 + j]  + g_ag[1][gb + 512 + j];
    float ghz = g_ag[0][gb + 1024 + j] + g_ag[1][gb + 1024 + j];
    float ghn = g_ag[0][gb + 1536 + j] + g_ag[1][gb + 1536 + j];
    float r = 1.f / (1.f + __expf(-(gir + ghr)));
    float z = 1.f / (1.f + __expf(-(giz + ghz)));
    float n = tanhf(gin + r * ghn);
    float h = g_h[idx];
    float hn = (1.f - z) * n + z * h;
    g_h[idx] = hn;
    __half h16 = __float2half_rn(hn);
    g_h16[idx] = h16;
    g_hall16[(t - 1) * (B_ * H_) + idx] = h16;
}

// ---------------- host -------------------------------------------------------
extern "C" void kernel_launch(void* const* d_in, const int* in_sizes, int n_in,
                              void* d_out, int out_size)
{
    const float* img = (const float*)d_in[0];
    const int*   cap = (const int*)d_in[1];
    const int*   cpl = (const int*)d_in[2];
    const float* emb = (const float*)d_in[3];
    const float* We  = (const float*)d_in[4];
    const float* be  = (const float*)d_in[5];
    const float* Wd  = (const float*)d_in[6];
    const float* bd  = (const float*)d_in[7];
    const float* Wf  = (const float*)d_in[8];
    const float* bfp = (const float*)d_in[9];
    const float* Wih = (const float*)d_in[10];
    const float* bih = (const float*)d_in[11];
    const float* Whh = (const float*)d_in[12];
    const float* bhh = (const float*)d_in[13];
    const float* Wo  = (const float*)d_in[14];
    const float* bo  = (const float*)d_in[15];
    float* out = (float*)d_out;

    static bool inited = false;
    static cudaStream_t s2 = nullptr;
    static cudaEvent_t eF = nullptr, eJ = nullptr, eP = nullptr;
    if (!inited) {
        cudaFuncSetAttribute(gemm2h, cudaFuncAttributeMaxDynamicSharedMemorySize, GEMMH_SMEM);
        cudaStreamCreateWithFlags(&s2, cudaStreamNonBlocking);
        cudaEventCreateWithFlags(&eF, cudaEventDisableTiming);
        cudaEventCreateWithFlags(&eJ, cudaEventDisableTiming);
        cudaEventCreateWithFlags(&eP, cudaEventDisableTiming);
        inited = true;
    }

    void *pImg16, *pAtt1h, *pWe16h, *pWe16l, *pBc16h, *pBc16l, *pBias;
    void *pWih16h, *pWih16l, *pWo16h, *pWo16l, *pXe16, *pGiE, *pAg, *pGi4, *pX16, *pH16, *pHa16;
    cudaGetSymbolAddress(&pImg16, g_img16);
    cudaGetSymbolAddress(&pAtt1h, g_att1h);
    cudaGetSymbolAddress(&pWe16h, g_WeT16h);  cudaGetSymbolAddress(&pWe16l, g_WeT16l);
    cudaGetSymbolAddress(&pBc16h, g_Bcat16h); cudaGetSymbolAddress(&pBc16l, g_Bcat16l);
    cudaGetSymbolAddress(&pBias, g_bias_cat);
    cudaGetSymbolAddress(&pWih16h, g_Wih16h); cudaGetSymbolAddress(&pWih16l, g_Wih16l);
    cudaGetSymbolAddress(&pWo16h, g_Wo16h);   cudaGetSymbolAddress(&pWo16l, g_Wo16l);
    cudaGetSymbolAddress(&pXe16, g_Xemb16);   cudaGetSymbolAddress(&pGiE, g_gi_emb);
    cudaGetSymbolAddress(&pAg, g_ag);         cudaGetSymbolAddress(&pGi4, g_gi4);
    cudaGetSymbolAddress(&pX16, g_x16);       cudaGetSymbolAddress(&pH16, g_h16);
    cudaGetSymbolAddress(&pHa16, g_hall16);

    // ---- prep (Wo split + emb gather forked onto s2, under att1) ----
    cudaEventRecord(eF, 0);
    cudaStreamWaitEvent(s2, eF, 0);
    {
        long n4 = (long)V_ * H_ / 4;
        split4h_k<<<(int)((n4 + 255) / 256), 256, 0, s2>>>(Wo, (__half*)pWo16h, (__half*)pWo16l, n4);
    }
    emb_gather_k<<<dim3(128, 19), 128, 0, s2>>>(emb, cap);
    cudaEventRecord(eP, s2);

    {
        long n4 = (long)M1_ * ENC_ / 4;
        prep_img_k<<<(int)((n4 + 255) / 256), 256>>>(img, n4);
    }
    transpose_split_h<<<dim3(16, 64), dim3(32, 8)>>>(We, (__half*)pWe16h, (__half*)pWe16l, 2048, 512);
    transpose_split_h<<<dim3(16, 16), dim3(32, 8)>>>(Wd, (__half*)pBc16h, (__half*)pBc16l, 512, 512);
    {
        long n4 = (long)H3_ * H_ / 4;
        split4h_k<<<(int)((n4 + 255) / 256), 256>>>(Whh, (__half*)pBc16h + 512 * 512, (__half*)pBc16l + 512 * 512, n4);
    }
    {
        long n4 = (long)H3_ * EX_ / 4;
        split4h_k<<<(int)((n4 + 255) / 256), 256>>>(Wih, (__half*)pWih16h, (__half*)pWih16l, n4);
    }
    biascat_k<<<8, 256>>>(bd, bhh);
    zero_h_k<<<256, 256>>>();
    {
        long tot = (long)B_ * V_ + B_ * P_ + B_;
        init_out_k<<<(int)((tot + 255) / 256), 256>>>(out, cpl);
    }

    // att1 = img16 @ WeT16^T + be -> fp16 [25088, 512]
    gemm2h<<<dim3(8, 196, 1), 256, GEMMH_SMEM>>>(
        (const __half*)pImg16, 2048, (const __half*)pWe16h, (const __half*)pWe16l, 2048,
        be, pAtt1h, (long)128 * 512, 512, 0, 512, 2048, 1, 0);

    // join: Xemb (and Wo) ready before gi_emb
    cudaStreamWaitEvent(0, eP, 0);

    // gi_emb = Xemb @ Wih[:, :512]^T + bih -> [2432, 1536] fp32
    gemm2h<<<dim3(24, 19, 1), 256, GEMMH_SMEM>>>(
        (const __half*)pXe16, 512, (const __half*)pWih16h, (const __half*)pWih16l, 2560,
        bih, pGiE, (long)128 * 1536, 1536, 0, 1536, 512, 0, 0);

    for (int t = 1; t < 20; t++) {
        // fork: gh = h16 @ Whh^T (+bhh) on s2 (cols 512..2047 of g_ag)
        cudaEventRecord(eF, 0);
        cudaStreamWaitEvent(s2, eF, 0);
        gemm2h<<<dim3(24, 1, 2), 256, GEMMH_SMEM, s2>>>(
            (const __half*)pH16, 512,
            (const __half*)pBc16h + (size_t)512 * 512, (const __half*)pBc16l + (size_t)512 * 512, 512,
            (const float*)pBias + 512, (float*)pAg + 512, 0, 2048, (long)B_ * 2048, 1536, 512, 0, 0);
        cudaEventRecord(eJ, s2);

        // critical path: att2 (cols 0..511) -> score -> ctx -> gi_ctx
        gemm2h<<<dim3(8, 1, 2), 256, GEMMH_SMEM>>>(
            (const __half*)pH16, 512, (const __half*)pBc16h, (const __half*)pBc16l, 512,
            (const float*)pBias, pAg, 0, 2048, (long)B_ * 2048, 512, 512, 0, 0);
        score_softmax_k<<<128, 256>>>(Wf, bfp, out, t);
        ctx_k<<<dim3(2, 128), 128>>>();
        gemm2h<<<dim3(24, 1, 4), 256, GEMMH_SMEM>>>(
            (const __half*)pX16, 2048, (const __half*)pWih16h + 512, (const __half*)pWih16l + 512, 2560,
            nullptr, pGi4, 0, 1536, (long)B_ * 1536, 1536, 2048, 0, 0);

        // join gh, then gates
        cudaStreamWaitEvent(0, eJ, 0);
        gates_k<<<256, 256>>>(t);
    }

    // preds (batched): [2432, 20000] -> out[b*400000 + t*20000 + v]
    gemm2h<<<dim3(19, 313, 1), 256, GEMMH_SMEM>>>(
        (const __half*)pHa16, 512, (const __half*)pWo16h, (const __half*)pWo16l, 512,
        bo, out + 20000, 20000, 400000, 0, 20000, 512, 0, 1);

    (void)in_sizes; (void)n_in; (void)out_size;
}

// round 13
// speedup vs baseline: 1.0926x; 1.0926x over previous
#include <cuda_runtime.h>
#include <cuda_bf16.h>
#include <cuda_fp16.h>
#include <cstdint>

static constexpr int B_ = 128, P_ = 196, ENC_ = 2048, A_ = 512, H_ = 512;
static constexpr int V_ = 20000, T_ = 20, H3_ = 1536, EX_ = 2560;
static constexpr long CAP_OFF   = (long)B_ * T_ * V_;   // 51,200,000
static constexpr long ALPHA_OFF = CAP_OFF + B_;         // 51,200,128
static constexpr int  M1_ = B_ * P_;                    // 25088
static constexpr int  MH_ = (T_ - 1) * B_;              // 2432

// ---------------- device scratch ------------------------------------------
__device__ __align__(16) __half g_img16[(size_t)M1_ * ENC_];
__device__ __align__(16) __half g_att1h[(size_t)M1_ * A_];
__device__ __align__(16) __half g_WeT16h[A_ * ENC_], g_WeT16l[A_ * ENC_];
__device__ __align__(16) __half g_Bcat16h[2048 * 512], g_Bcat16l[2048 * 512];
__device__ __align__(16) float  g_bias_cat[2048];
__device__ __align__(16) __half g_Wih16h[H3_ * EX_], g_Wih16l[H3_ * EX_];
__device__ __align__(16) __half g_Wo16h[(size_t)V_ * H_], g_Wo16l[(size_t)V_ * H_];
__device__ __align__(16) __half g_Xemb16[MH_ * 512];
__device__ __align__(16) float  g_gi_emb[(size_t)MH_ * H3_];
__device__ __align__(16) float  g_ag0[B_ * 2048];       // att2|gh (full-K)
__device__ __align__(16) float  g_gi4[2][B_ * H3_];     // split-K partials: gi_ctx
__device__ __align__(16) float  g_alpha[B_ * P_];
__device__ __align__(16) __half g_x16[B_ * ENC_];       // ctx fp16
__device__ __align__(16) float  g_h[B_ * H_];
__device__ __align__(16) __half g_h16[B_ * H_];
__device__ __align__(16) __half g_hall16[MH_ * H_];
__device__ int g_bar_cnt = 0;
__device__ int g_bar_gen = 0;

// ---------------- helpers --------------------------------------------------
__device__ __forceinline__ uint32_t s2u(const void* p) {
    return (uint32_t)__cvta_generic_to_shared(p);
}
__device__ __forceinline__ void ldsm4(uint32_t r[4], uint32_t a) {
    asm volatile("ldmatrix.sync.aligned.m8n8.x4.shared.b16 {%0,%1,%2,%3},[%4];"
                 : "=r"(r[0]), "=r"(r[1]), "=r"(r[2]), "=r"(r[3]) : "r"(a));
}
__device__ __forceinline__ void mma16816h(float c[4], const uint32_t a[4], const uint32_t b[2]) {
    asm volatile(
        "mma.sync.aligned.m16n8k16.row.col.f32.f16.f16.f32 "
        "{%0,%1,%2,%3},{%4,%5,%6,%7},{%8,%9},{%0,%1,%2,%3};"
        : "+f"(c[0]), "+f"(c[1]), "+f"(c[2]), "+f"(c[3])
        : "r"(a[0]), "r"(a[1]), "r"(a[2]), "r"(a[3]), "r"(b[0]), "r"(b[1]));
}
#define CP16(d, s) asm volatile("cp.async.cg.shared.global [%0],[%1],16;\n" :: "r"(d), "l"(s))
#define CPCOMMIT() asm volatile("cp.async.commit_group;\n")

__device__ __forceinline__ void split2h(float v, __half& h, __half& l) {
    h = __float2half_rn(v);
    l = __float2half_rn(v - __half2float(h));
}

// grid-wide barrier: all gridDim.x blocks are co-resident (grid <= SM count x2)
__device__ __forceinline__ void grid_bar(int nb) {
    __syncthreads();
    if (threadIdx.x == 0) {
        int gen = *(volatile int*)&g_bar_gen;
        __threadfence();
        if (atomicAdd(&g_bar_cnt, 1) == nb - 1) {
            g_bar_cnt = 0;
            __threadfence();
            *(volatile int*)&g_bar_gen = gen + 1;
        } else {
            while (*(volatile int*)&g_bar_gen == gen) { }
        }
        __threadfence();
    }
    __syncthreads();
}

// ---------------- fp16 2-MMA GEMM: C = A16 @ (Bh+Bl)^T (+bias) --------------
static constexpr int HSA = 128 * 40;
static constexpr int HSB = 64 * 40;
static constexpr int HSTG = HSA + 2 * HSB;       // 10240 halves
static constexpr int GEMMH_SMEM = 2 * HSTG * 2;  // 40960 B

// device-side tile worker: M=128 rows (m0 given), one 64-col N tile, K range.
__device__ void gemm_tile(
    const __half* __restrict__ Ag, int lda, int m0,
    const __half* __restrict__ Bgh, const __half* __restrict__ Bgl, int ldb,
    const float* __restrict__ bias, float* __restrict__ C, long row_stride,
    int n0, int kbase, int Ksub, __half* smh)
{
    const int tid = threadIdx.x, lane = tid & 31, warp = tid >> 5;
    const int wm = warp >> 1, wn = warp & 1;

    float acc[2][4][4];
#pragma unroll
    for (int i = 0; i < 2; i++)
#pragma unroll
        for (int j = 0; j < 4; j++)
#pragma unroll
            for (int k = 0; k < 4; k++) acc[i][j][k] = 0.f;

    auto load_stage = [&](int st, int k0) {
        __half* As  = smh + st * HSTG;
        __half* Bsh = As + HSA;
        __half* Bsl = Bsh + HSB;
#pragma unroll
        for (int it = 0; it < 2; it++) {
            int idx = tid + it * 256, r = idx >> 2, ch = idx & 3;
            CP16(s2u(As + r * 40 + ch * 8), Ag + (size_t)(m0 + r) * lda + kbase + k0 + ch * 8);
        }
        {
            int r = tid >> 2, ch = tid & 3;
            size_t go = (size_t)(n0 + r) * ldb + kbase + k0 + ch * 8;
            CP16(s2u(Bsh + r * 40 + ch * 8), Bgh + go);
            CP16(s2u(Bsl + r * 40 + ch * 8), Bgl + go);
        }
        CPCOMMIT();
    };

    const int nk = Ksub / 32;
    load_stage(0, 0);
    for (int i = 0; i < nk; i++) {
        if (i + 1 < nk) {
            load_stage((i + 1) & 1, (i + 1) * 32);
            asm volatile("cp.async.wait_group 1;\n");
        } else {
            asm volatile("cp.async.wait_group 0;\n");
        }
        __syncthreads();
        __half* As  = smh + (i & 1) * HSTG;
        __half* Bsh = As + HSA;
        __half* Bsl = Bsh + HSB;
#pragma unroll
        for (int kk = 0; kk < 32; kk += 16) {
            uint32_t ah[2][4], bh[4][2], bl[4][2];
#pragma unroll
            for (int mt = 0; mt < 2; mt++) {
                int off = (wm * 32 + mt * 16 + (lane & 15)) * 40 + kk + ((lane >> 4) << 3);
                ldsm4(ah[mt], s2u(As + off));
            }
#pragma unroll
            for (int ng = 0; ng < 2; ng++) {
                int off = (wn * 32 + ng * 16 + (lane & 15)) * 40 + kk + ((lane >> 4) << 3);
                uint32_t t4[4];
                ldsm4(t4, s2u(Bsh + off));
                bh[ng * 2][0] = t4[0]; bh[ng * 2][1] = t4[2];
                bh[ng * 2 + 1][0] = t4[1]; bh[ng * 2 + 1][1] = t4[3];
                ldsm4(t4, s2u(Bsl + off));
                bl[ng * 2][0] = t4[0]; bl[ng * 2][1] = t4[2];
                bl[ng * 2 + 1][0] = t4[1]; bl[ng * 2 + 1][1] = t4[3];
            }
#pragma unroll
            for (int mt = 0; mt < 2; mt++)
#pragma unroll
                for (int nt = 0; nt < 4; nt++) {
                    mma16816h(acc[mt][nt], ah[mt], bh[nt]);
                    mma16816h(acc[mt][nt], ah[mt], bl[nt]);
                }
        }
        __syncthreads();
    }

    const bool addb = (bias != nullptr);
#pragma unroll
    for (int mt = 0; mt < 2; mt++) {
        int r = wm * 32 + mt * 16 + (lane >> 2);
#pragma unroll
        for (int nt = 0; nt < 4; nt++) {
            int col = n0 + wn * 32 + nt * 8 + (lane & 3) * 2;
            float b0 = addb ? bias[col] : 0.f;
            float b1 = addb ? bias[col + 1] : 0.f;
            C[(long)r * row_stride + col]           = acc[mt][nt][0] + b0;
            C[(long)(r + 8) * row_stride + col]     = acc[mt][nt][2] + b0;
            C[(long)r * row_stride + col + 1]       = acc[mt][nt][1] + b1;
            C[(long)(r + 8) * row_stride + col + 1] = acc[mt][nt][3] + b1;
        }
    }
}

// ---------------- host-callable GEMM (fixed parts) --------------------------
__global__ __launch_bounds__(256) void gemm2h(
    const __half* __restrict__ Ag, int lda,
    const __half* __restrict__ Bgh, const __half* __restrict__ Bgl, int ldb,
    const float* __restrict__ bias, void* __restrict__ Cbase,
    long tile_stride, long row_stride, long part_stride,
    int N, int Ktot, int out_half, int swap_xy)
{
    extern __shared__ __align__(16) __half smh[];
    const int tid = threadIdx.x, lane = tid & 31, warp = tid >> 5;
    const int wm = warp >> 1, wn = warp & 1;
    const int bx = swap_xy ? blockIdx.y : blockIdx.x;
    const int by = swap_xy ? blockIdx.x : blockIdx.y;
    const int n0 = bx * 64, m0 = by * 128;
    const int ks = blockIdx.z;
    const int Ksub = Ktot / gridDim.z, kbase = ks * Ksub;

    float acc[2][4][4];
#pragma unroll
    for (int i = 0; i < 2; i++)
#pragma unroll
        for (int j = 0; j < 4; j++)
#pragma unroll
            for (int k = 0; k < 4; k++) acc[i][j][k] = 0.f;

    auto load_stage = [&](int st, int k0) {
        __half* As  = smh + st * HSTG;
        __half* Bsh = As + HSA;
        __half* Bsl = Bsh + HSB;
#pragma unroll
        for (int it = 0; it < 2; it++) {
            int idx = tid + it * 256, r = idx >> 2, ch = idx & 3;
            CP16(s2u(As + r * 40 + ch * 8), Ag + (size_t)(m0 + r) * lda + k0 + ch * 8);
        }
        {
            int r = tid >> 2, ch = tid & 3;
            int rr = (n0 + r < N) ? (n0 + r) : (N - 1);
            size_t go = (size_t)rr * ldb + k0 + ch * 8;
            CP16(s2u(Bsh + r * 40 + ch * 8), Bgh + go);
            CP16(s2u(Bsl + r * 40 + ch * 8), Bgl + go);
        }
        CPCOMMIT();
    };

    const int nk = Ksub / 32;
    load_stage(0, kbase);
    for (int i = 0; i < nk; i++) {
        if (i + 1 < nk) {
            load_stage((i + 1) & 1, kbase + (i + 1) * 32);
            asm volatile("cp.async.wait_group 1;\n");
        } else {
            asm volatile("cp.async.wait_group 0;\n");
        }
        __syncthreads();
        __half* As  = smh + (i & 1) * HSTG;
        __half* Bsh = As + HSA;
        __half* Bsl = Bsh + HSB;
#pragma unroll
        for (int kk = 0; kk < 32; kk += 16) {
            uint32_t ah[2][4], bh[4][2], bl[4][2];
#pragma unroll
            for (int mt = 0; mt < 2; mt++) {
                int off = (wm * 32 + mt * 16 + (lane & 15)) * 40 + kk + ((lane >> 4) << 3);
                ldsm4(ah[mt], s2u(As + off));
            }
#pragma unroll
            for (int ng = 0; ng < 2; ng++) {
                int off = (wn * 32 + ng * 16 + (lane & 15)) * 40 + kk + ((lane >> 4) << 3);
                uint32_t t4[4];
                ldsm4(t4, s2u(Bsh + off));
                bh[ng * 2][0] = t4[0]; bh[ng * 2][1] = t4[2];
                bh[ng * 2 + 1][0] = t4[1]; bh[ng * 2 + 1][1] = t4[3];
                ldsm4(t4, s2u(Bsl + off));
                bl[ng * 2][0] = t4[0]; bl[ng * 2][1] = t4[2];
                bl[ng * 2 + 1][0] = t4[1]; bl[ng * 2 + 1][1] = t4[3];
            }
#pragma unroll
            for (int mt = 0; mt < 2; mt++)
#pragma unroll
                for (int nt = 0; nt < 4; nt++) {
                    mma16816h(acc[mt][nt], ah[mt], bh[nt]);
                    mma16816h(acc[mt][nt], ah[mt], bl[nt]);
                }
        }
        __syncthreads();
    }

    const bool addb = (bias != nullptr) && (ks == 0);
    if (!out_half) {
        float* Cp = (float*)Cbase + (long)by * tile_stride + (long)ks * part_stride;
#pragma unroll
        for (int mt = 0; mt < 2; mt++) {
            int r = wm * 32 + mt * 16 + (lane >> 2);
#pragma unroll
            for (int nt = 0; nt < 4; nt++) {
                int col = n0 + wn * 32 + nt * 8 + (lane & 3) * 2;
                if (col < N) {
                    float bb = addb ? bias[col] : 0.f;
                    Cp[(long)r * row_stride + col]       = acc[mt][nt][0] + bb;
                    Cp[(long)(r + 8) * row_stride + col] = acc[mt][nt][2] + bb;
                }
                if (col + 1 < N) {
                    float bb = addb ? bias[col + 1] : 0.f;
                    Cp[(long)r * row_stride + col + 1]       = acc[mt][nt][1] + bb;
                    Cp[(long)(r + 8) * row_stride + col + 1] = acc[mt][nt][3] + bb;
                }
            }
        }
    } else {
        __half* Cp = (__half*)Cbase + (long)by * tile_stride + (long)ks * part_stride;
#pragma unroll
        for (int mt = 0; mt < 2; mt++) {
            int r = wm * 32 + mt * 16 + (lane >> 2);
#pragma unroll
            for (int nt = 0; nt < 4; nt++) {
                int col = n0 + wn * 32 + nt * 8 + (lane & 3) * 2;
                float b0 = addb ? bias[col] : 0.f;
                float b1 = addb ? bias[col + 1] : 0.f;
                __half2 w0 = {__float2half_rn(acc[mt][nt][0] + b0), __float2half_rn(acc[mt][nt][1] + b1)};
                __half2 w1 = {__float2half_rn(acc[mt][nt][2] + b0), __float2half_rn(acc[mt][nt][3] + b1)};
                *(__half2*)(Cp + (long)r * row_stride + col)       = w0;
                *(__half2*)(Cp + (long)(r + 8) * row_stride + col) = w1;
            }
        }
    }
}

// ---------------- fused per-step kernel (1 launch/step) ----------------------
// grid = 128 blocks x 256 threads; all blocks co-resident -> grid_bar is safe.
__global__ __launch_bounds__(256) void step_k(
    const float* __restrict__ wf, const float* __restrict__ bfp,
    float* __restrict__ out, int t)
{
    extern __shared__ __align__(16) __half smh[];
    const int bid = blockIdx.x, tid = threadIdx.x;
    const int nb = gridDim.x;

    // ---- Phase A: [att2|gh] = h16 @ Bcat^T + biascat  (32 tiles, K=512) ----
    if (bid < 32) {
        gemm_tile(g_h16, 512, 0, g_Bcat16h, g_Bcat16l, 512,
                  g_bias_cat, g_ag0, 2048, bid * 64, 0, 512, smh);
    }
    grid_bar(nb);

    // ---- Phase B: score + softmax (one block per batch) ----
    {
        __shared__ float att2s[512], wfs[512], sc[200], red[256];
        const int b = bid, lane = tid & 31, warp = tid >> 5;
        for (int i = tid; i < 512; i += 256) {
            att2s[i] = g_ag0[b * 2048 + i];
            wfs[i] = wf[i];
        }
        __syncthreads();
        const float bfv = bfp[0];
        for (int p = warp; p < 196; p += 8) {
            const __half2* row = (const __half2*)(g_att1h + ((size_t)b * 196 + p) * 512);
            float s = 0.f;
#pragma unroll
            for (int i = 0; i < 8; i++) {
                int c = lane + i * 32;
                float2 vf = __half22float2(row[c]);
                s += fmaxf(vf.x + att2s[2 * c], 0.f) * wfs[2 * c]
                   + fmaxf(vf.y + att2s[2 * c + 1], 0.f) * wfs[2 * c + 1];
            }
#pragma unroll
            for (int o = 16; o; o >>= 1) s += __shfl_xor_sync(0xffffffffu, s, o);
            if (lane == 0) sc[p] = s + bfv;
        }
        __syncthreads();
        float v = (tid < 196) ? sc[tid] : -1e30f;
        red[tid] = v; __syncthreads();
        for (int o = 128; o; o >>= 1) { if (tid < o) red[tid] = fmaxf(red[tid], red[tid + o]); __syncthreads(); }
        float m = red[0]; __syncthreads();
        float e = (tid < 196) ? __expf(sc[tid] - m) : 0.f;
        red[tid] = e; __syncthreads();
        for (int o = 128; o; o >>= 1) { if (tid < o) red[tid] += red[tid + o]; __syncthreads(); }
        float inv = 1.f / red[0];
        if (tid < 196) {
            float a = e * inv;
            g_alpha[b * 196 + tid] = a;
            out[ALPHA_OFF + ((size_t)b * 20 + t) * 196 + tid] = a;
        }
    }
    grid_bar(nb);

    // ---- Phase C: ctx weighted sum (one block per batch, 256 uint4 cols) ----
    {
        __shared__ float al[196];
        const int b = bid;
        for (int i = tid; i < 196; i += 256) al[i] = g_alpha[b * 196 + i];
        __syncthreads();
        const uint4* ip = (const uint4*)(g_img16 + (size_t)b * 196 * 2048);
        const int c0 = tid;  // 0..255
        float acc[8] = {0.f};
#pragma unroll 4
        for (int p = 0; p < 196; p++) {
            uint4 v = ip[(size_t)p * 256 + c0];
            float a = al[p];
            float2 f;
            f = __half22float2(*(__half2*)&v.x); acc[0] += a * f.x; acc[1] += a * f.y;
            f = __half22float2(*(__half2*)&v.y); acc[2] += a * f.x; acc[3] += a * f.y;
            f = __half22float2(*(__half2*)&v.z); acc[4] += a * f.x; acc[5] += a * f.y;
            f = __half22float2(*(__half2*)&v.w); acc[6] += a * f.x; acc[7] += a * f.y;
        }
        uint4 o;
        *(__half2*)&o.x = {__float2half_rn(acc[0]), __float2half_rn(acc[1])};
        *(__half2*)&o.y = {__float2half_rn(acc[2]), __float2half_rn(acc[3])};
        *(__half2*)&o.z = {__float2half_rn(acc[4]), __float2half_rn(acc[5])};
        *(__half2*)&o.w = {__float2half_rn(acc[6]), __float2half_rn(acc[7])};
        ((uint4*)(g_x16 + b * 2048))[c0] = o;
    }
    grid_bar(nb);

    // ---- Phase D: gi_ctx = x16 @ Wih[:,512:]^T (24 tiles x splitK2) ----
    if (bid < 48) {
        int ks = bid & 1, nt = bid >> 1;
        gemm_tile(g_x16, 2048, 0, g_Wih16h + 512, g_Wih16l + 512, 2560,
                  nullptr, g_gi4[ks], 1536, nt * 64, ks * 1024, 1024, smh);
    }
    grid_bar(nb);

    // ---- Phase E: gates ----
    for (int e = bid * 256 + tid; e < B_ * H_; e += nb * 256) {
        int b = e >> 9, j = e & 511;
        const float* ge = g_gi_emb + (size_t)((t - 1) * 128 + b) * 1536;
        int base = b * 1536;
        float gir = ge[j]        + g_gi4[0][base + j]        + g_gi4[1][base + j];
        float giz = ge[512 + j]  + g_gi4[0][base + 512 + j]  + g_gi4[1][base + 512 + j];
        float gin = ge[1024 + j] + g_gi4[0][base + 1024 + j] + g_gi4[1][base + 1024 + j];
        int gb = b * 2048;
        float ghr = g_ag0[gb + 512 + j];
        float ghz = g_ag0[gb + 1024 + j];
        float ghn = g_ag0[gb + 1536 + j];
        float r = 1.f / (1.f + __expf(-(gir + ghr)));
        float z = 1.f / (1.f + __expf(-(giz + ghz)));
        float n = tanhf(gin + r * ghn);
        float h = g_h[e];
        float hn = (1.f - z) * n + z * h;
        g_h[e] = hn;
        __half h16 = __float2half_rn(hn);
        g_h16[e] = h16;
        g_hall16[(t - 1) * (B_ * H_) + e] = h16;
    }
}

// ---------------- prep kernels ----------------------------------------------
__global__ void prep_img_k(const float* __restrict__ src, long n4)
{
    long i = (long)blockIdx.x * 256 + threadIdx.x;
    if (i >= n4) return;
    float4 v = ((const float4*)src)[i];
    ((__half2*)(g_img16 + 4 * i))[0] = {__float2half_rn(v.x), __float2half_rn(v.y)};
    ((__half2*)(g_img16 + 4 * i))[1] = {__float2half_rn(v.z), __float2half_rn(v.w)};
}

__global__ void split4h_k(const float* __restrict__ src, __half* __restrict__ dh,
                          __half* __restrict__ dl, long n4)
{
    long i = (long)blockIdx.x * 256 + threadIdx.x;
    if (i >= n4) return;
    float4 v = ((const float4*)src)[i];
    __half h0, h1, h2, h3, l0, l1, l2, l3;
    split2h(v.x, h0, l0); split2h(v.y, h1, l1); split2h(v.z, h2, l2); split2h(v.w, h3, l3);
    ((__half2*)(dh + 4 * i))[0] = {h0, h1};
    ((__half2*)(dh + 4 * i))[1] = {h2, h3};
    ((__half2*)(dl + 4 * i))[0] = {l0, l1};
    ((__half2*)(dl + 4 * i))[1] = {l2, l3};
}

__global__ void transpose_split_h(const float* __restrict__ src, __half* __restrict__ dh,
                                  __half* __restrict__ dl, int R, int C)
{
    __shared__ float tile[32][33];
    int c0 = blockIdx.x * 32, r0 = blockIdx.y * 32;
    int tx = threadIdx.x, ty = threadIdx.y;  // (32, 8)
#pragma unroll
    for (int i = 0; i < 4; i++) {
        int r = r0 + ty + i * 8;
        if (r < R && c0 + tx < C) tile[ty + i * 8][tx] = src[(size_t)r * C + c0 + tx];
    }
    __syncthreads();
#pragma unroll
    for (int i = 0; i < 4; i++) {
        int orow = c0 + ty + i * 8, ocol = r0 + tx;
        if (orow < C && ocol < R) {
            __half h, l;
            split2h(tile[tx][ty + i * 8], h, l);
            dh[(size_t)orow * R + ocol] = h;
            dl[(size_t)orow * R + ocol] = l;
        }
    }
}

__global__ void emb_gather_k(const float* __restrict__ emb, const int* __restrict__ cap)
{
    const int b = blockIdx.x, tt = blockIdx.y;   // tt = t-1, 0..18
    const int w = cap[b * 20 + tt];
    __half* dst = g_Xemb16 + (size_t)(tt * 128 + b) * 512;
    const float* s = emb + (size_t)w * 512;
    for (int i = threadIdx.x; i < 512; i += 128) dst[i] = __float2half_rn(s[i]);
}

__global__ void biascat_k(const float* __restrict__ bd, const float* __restrict__ bhh)
{
    int i = blockIdx.x * 256 + threadIdx.x;
    if (i < 512) g_bias_cat[i] = bd[i];
    else if (i < 2048) g_bias_cat[i] = bhh[i - 512];
}

__global__ void zero_h_k()
{
    int i = blockIdx.x * 256 + threadIdx.x;
    if (i < B_ * H_) { g_h[i] = 0.f; g_h16[i] = __float2half_rn(0.f); }
    if (i == 0) { g_bar_cnt = 0; }
}

__global__ void init_out_k(float* __restrict__ out, const int* __restrict__ caplen)
{
    long i = (long)blockIdx.x * 256 + threadIdx.x;
    const long n0 = (long)B_ * V_;
    if (i < n0) {
        long b = i / V_, v2 = i % V_;
        out[b * 400000 + v2] = (v2 == 1) ? 1.f : 0.f;
    } else if (i < n0 + B_ * P_) {
        long j = i - n0, b = j / P_, p = j % P_;
        out[ALPHA_OFF + b * (T_ * P_) + p] = 0.f;
    } else if (i < n0 + B_ * P_ + B_) {
        int b = (int)(i - n0 - B_ * P_);
        out[CAP_OFF + b] = (float)caplen[b];
    }
}

// ---------------- host -------------------------------------------------------
extern "C" void kernel_launch(void* const* d_in, const int* in_sizes, int n_in,
                              void* d_out, int out_size)
{
    const float* img = (const float*)d_in[0];
    const int*   cap = (const int*)d_in[1];
    const int*   cpl = (const int*)d_in[2];
    const float* emb = (const float*)d_in[3];
    const float* We  = (const float*)d_in[4];
    const float* be  = (const float*)d_in[5];
    const float* Wd  = (const float*)d_in[6];
    const float* bd  = (const float*)d_in[7];
    const float* Wf  = (const float*)d_in[8];
    const float* bfp = (const float*)d_in[9];
    const float* Wih = (const float*)d_in[10];
    const float* bih = (const float*)d_in[11];
    const float* Whh = (const float*)d_in[12];
    const float* bhh = (const float*)d_in[13];
    const float* Wo  = (const float*)d_in[14];
    const float* bo  = (const float*)d_in[15];
    float* out = (float*)d_out;

    static bool inited = false;
    if (!inited) {
        cudaFuncSetAttribute(gemm2h, cudaFuncAttributeMaxDynamicSharedMemorySize, GEMMH_SMEM);
        cudaFuncSetAttribute(step_k, cudaFuncAttributeMaxDynamicSharedMemorySize, GEMMH_SMEM);
        inited = true;
    }

    void *pImg16, *pAtt1h, *pWe16h, *pWe16l, *pBc16h, *pBc16l;
    void *pWih16h, *pWih16l, *pWo16h, *pWo16l, *pXe16, *pGiE, *pHa16;
    cudaGetSymbolAddress(&pImg16, g_img16);
    cudaGetSymbolAddress(&pAtt1h, g_att1h);
    cudaGetSymbolAddress(&pWe16h, g_WeT16h);  cudaGetSymbolAddress(&pWe16l, g_WeT16l);
    cudaGetSymbolAddress(&pBc16h, g_Bcat16h); cudaGetSymbolAddress(&pBc16l, g_Bcat16l);
    cudaGetSymbolAddress(&pWih16h, g_Wih16h); cudaGetSymbolAddress(&pWih16l, g_Wih16l);
    cudaGetSymbolAddress(&pWo16h, g_Wo16h);   cudaGetSymbolAddress(&pWo16l, g_Wo16l);
    cudaGetSymbolAddress(&pXe16, g_Xemb16);   cudaGetSymbolAddress(&pGiE, g_gi_emb);
    cudaGetSymbolAddress(&pHa16, g_hall16);

    // ---- prep ----
    {
        long n4 = (long)M1_ * ENC_ / 4;
        prep_img_k<<<(int)((n4 + 255) / 256), 256>>>(img, n4);
    }
    transpose_split_h<<<dim3(16, 64), dim3(32, 8)>>>(We, (__half*)pWe16h, (__half*)pWe16l, 2048, 512);
    transpose_split_h<<<dim3(16, 16), dim3(32, 8)>>>(Wd, (__half*)pBc16h, (__half*)pBc16l, 512, 512);
    {
        long n4 = (long)H3_ * H_ / 4;
        split4h_k<<<(int)((n4 + 255) / 256), 256>>>(Whh, (__half*)pBc16h + 512 * 512, (__half*)pBc16l + 512 * 512, n4);
    }
    {
        long n4 = (long)H3_ * EX_ / 4;
        split4h_k<<<(int)((n4 + 255) / 256), 256>>>(Wih, (__half*)pWih16h, (__half*)pWih16l, n4);
    }
    {
        long n4 = (long)V_ * H_ / 4;
        split4h_k<<<(int)((n4 + 255) / 256), 256>>>(Wo, (__half*)pWo16h, (__half*)pWo16l, n4);
    }
    emb_gather_k<<<dim3(128, 19), 128>>>(emb, cap);
    biascat_k<<<8, 256>>>(bd, bhh);
    zero_h_k<<<256, 256>>>();
    {
        long tot = (long)B_ * V_ + B_ * P_ + B_;
        init_out_k<<<(int)((tot + 255) / 256), 256>>>(out, cpl);
    }

    // att1 = img16 @ WeT16^T + be -> fp16 [25088, 512]
    gemm2h<<<dim3(8, 196, 1), 256, GEMMH_SMEM>>>(
        (const __half*)pImg16, 2048, (const __half*)pWe16h, (const __half*)pWe16l, 2048,
        be, pAtt1h, (long)128 * 512, 512, 0, 512, 2048, 1, 0);

    // gi_emb = Xemb @ Wih[:, :512]^T + bih -> [2432, 1536] fp32
    gemm2h<<<dim3(24, 19, 1), 256, GEMMH_SMEM>>>(
        (const __half*)pXe16, 512, (const __half*)pWih16h, (const __half*)pWih16l, 2560,
        bih, pGiE, (long)128 * 1536, 1536, 0, 1536, 512, 0, 0);

    // fused per-step pipeline: one launch per step
    for (int t = 1; t < 20; t++) {
        step_k<<<128, 256, GEMMH_SMEM>>>(Wf, bfp, out, t);
    }

    // preds (batched): [2432, 20000] -> out[b*400000 + t*20000 + v]
    gemm2h<<<dim3(313, 19, 1), 256, GEMMH_SMEM>>>(
        (const __half*)pHa16, 512, (const __half*)pWo16h, (const __half*)pWo16l, 512,
        bo, out + 20000, 20000, 400000, 0, 20000, 512, 0, 0);

    (void)in_sizes; (void)n_in; (void)out_size;
}

// round 14
// speedup vs baseline: 1.2538x; 1.1476x over previous
#include <cuda_runtime.h>
#include <cuda_bf16.h>
#include <cuda_fp16.h>
#include <cstdint>

static constexpr int B_ = 128, P_ = 196, ENC_ = 2048, A_ = 512, H_ = 512;
static constexpr int V_ = 20000, T_ = 20, H3_ = 1536, EX_ = 2560;
static constexpr long CAP_OFF   = (long)B_ * T_ * V_;   // 51,200,000
static constexpr long ALPHA_OFF = CAP_OFF + B_;         // 51,200,128
static constexpr int  M1_ = B_ * P_;                    // 25088
static constexpr int  MH_ = (T_ - 1) * B_;              // 2432

// ---------------- device scratch ------------------------------------------
__device__ __align__(16) __half g_img16[(size_t)M1_ * ENC_];
__device__ __align__(16) __half g_att1h[(size_t)M1_ * A_];
__device__ __align__(16) __half g_WeT16h[A_ * ENC_], g_WeT16l[A_ * ENC_];
__device__ __align__(16) __half g_Bcat16h[2048 * 512], g_Bcat16l[2048 * 512];
__device__ __align__(16) float  g_bias_cat[2048];
__device__ __align__(16) __half g_Wih16h[H3_ * EX_], g_Wih16l[H3_ * EX_];
__device__ __align__(16) __half g_Wo16[(size_t)V_ * H_];
__device__ __align__(16) __half g_Xemb16[MH_ * 512];
__device__ __align__(16) float  g_gi_emb[(size_t)MH_ * H3_];
__device__ __align__(16) float  g_ag[2][B_ * 2048];     // split-K partials: att2|gh
__device__ __align__(16) float  g_gi4[4][B_ * H3_];     // split-K partials: gi_ctx
__device__ __align__(16) float  g_alpha[B_ * P_];
__device__ __align__(16) __half g_x16[B_ * ENC_];       // ctx fp16
__device__ __align__(16) float  g_h[B_ * H_];
__device__ __align__(16) __half g_h16[B_ * H_];
__device__ __align__(16) __half g_hall16[MH_ * H_];

// ---------------- helpers --------------------------------------------------
__device__ __forceinline__ uint32_t s2u(const void* p) {
    return (uint32_t)__cvta_generic_to_shared(p);
}
__device__ __forceinline__ void ldsm4(uint32_t r[4], uint32_t a) {
    asm volatile("ldmatrix.sync.aligned.m8n8.x4.shared.b16 {%0,%1,%2,%3},[%4];"
                 : "=r"(r[0]), "=r"(r[1]), "=r"(r[2]), "=r"(r[3]) : "r"(a));
}
__device__ __forceinline__ void mma16816h(float c[4], const uint32_t a[4], const uint32_t b[2]) {
    asm volatile(
        "mma.sync.aligned.m16n8k16.row.col.f32.f16.f16.f32 "
        "{%0,%1,%2,%3},{%4,%5,%6,%7},{%8,%9},{%0,%1,%2,%3};"
        : "+f"(c[0]), "+f"(c[1]), "+f"(c[2]), "+f"(c[3])
        : "r"(a[0]), "r"(a[1]), "r"(a[2]), "r"(a[3]), "r"(b[0]), "r"(b[1]));
}
#define CP16(d, s) asm volatile("cp.async.cg.shared.global [%0],[%1],16;\n" :: "r"(d), "l"(s))
#define CPCOMMIT() asm volatile("cp.async.commit_group;\n")

__device__ __forceinline__ void split2h(float v, __half& h, __half& l) {
    h = __float2half_rn(v);
    l = __float2half_rn(v - __half2float(h));
}

// ---------------- fp16 2-MMA GEMM (split-B, per-step + gi_emb) --------------
static constexpr int HSA = 128 * 40;
static constexpr int HSB = 64 * 40;
static constexpr int HSTG = HSA + 2 * HSB;       // 10240 halves
static constexpr int GEMMH_SMEM = 2 * HSTG * 2;  // 40960 B

__global__ __launch_bounds__(256) void gemm2h(
    const __half* __restrict__ Ag, int lda,
    const __half* __restrict__ Bgh, const __half* __restrict__ Bgl, int ldb,
    const float* __restrict__ bias, void* __restrict__ Cbase,
    long tile_stride, long row_stride, long part_stride,
    int N, int Ktot, int out_half)
{
    extern __shared__ __align__(16) __half smh[];
    const int tid = threadIdx.x, lane = tid & 31, warp = tid >> 5;
    const int wm = warp >> 1, wn = warp & 1;
    const int n0 = blockIdx.x * 64, m0 = blockIdx.y * 128;
    const int ks = blockIdx.z;
    const int Ksub = Ktot / gridDim.z, kbase = ks * Ksub;

    float acc[2][4][4];
#pragma unroll
    for (int i = 0; i < 2; i++)
#pragma unroll
        for (int j = 0; j < 4; j++)
#pragma unroll
            for (int k = 0; k < 4; k++) acc[i][j][k] = 0.f;

    auto load_stage = [&](int st, int k0) {
        __half* As  = smh + st * HSTG;
        __half* Bsh = As + HSA;
        __half* Bsl = Bsh + HSB;
#pragma unroll
        for (int it = 0; it < 2; it++) {
            int idx = tid + it * 256, r = idx >> 2, ch = idx & 3;
            CP16(s2u(As + r * 40 + ch * 8), Ag + (size_t)(m0 + r) * lda + k0 + ch * 8);
        }
        {
            int r = tid >> 2, ch = tid & 3;
            int rr = (n0 + r < N) ? (n0 + r) : (N - 1);
            size_t go = (size_t)rr * ldb + k0 + ch * 8;
            CP16(s2u(Bsh + r * 40 + ch * 8), Bgh + go);
            CP16(s2u(Bsl + r * 40 + ch * 8), Bgl + go);
        }
        CPCOMMIT();
    };

    const int nk = Ksub / 32;
    load_stage(0, kbase);
    for (int i = 0; i < nk; i++) {
        if (i + 1 < nk) {
            load_stage((i + 1) & 1, kbase + (i + 1) * 32);
            asm volatile("cp.async.wait_group 1;\n");
        } else {
            asm volatile("cp.async.wait_group 0;\n");
        }
        __syncthreads();
        __half* As  = smh + (i & 1) * HSTG;
        __half* Bsh = As + HSA;
        __half* Bsl = Bsh + HSB;
#pragma unroll
        for (int kk = 0; kk < 32; kk += 16) {
            uint32_t ah[2][4], bh[4][2], bl[4][2];
#pragma unroll
            for (int mt = 0; mt < 2; mt++) {
                int off = (wm * 32 + mt * 16 + (lane & 15)) * 40 + kk + ((lane >> 4) << 3);
                ldsm4(ah[mt], s2u(As + off));
            }
#pragma unroll
            for (int ng = 0; ng < 2; ng++) {
                int off = (wn * 32 + ng * 16 + (lane & 15)) * 40 + kk + ((lane >> 4) << 3);
                uint32_t t4[4];
                ldsm4(t4, s2u(Bsh + off));
                bh[ng * 2][0] = t4[0]; bh[ng * 2][1] = t4[2];
                bh[ng * 2 + 1][0] = t4[1]; bh[ng * 2 + 1][1] = t4[3];
                ldsm4(t4, s2u(Bsl + off));
                bl[ng * 2][0] = t4[0]; bl[ng * 2][1] = t4[2];
                bl[ng * 2 + 1][0] = t4[1]; bl[ng * 2 + 1][1] = t4[3];
            }
#pragma unroll
            for (int mt = 0; mt < 2; mt++)
#pragma unroll
                for (int nt = 0; nt < 4; nt++) {
                    mma16816h(acc[mt][nt], ah[mt], bh[nt]);
                    mma16816h(acc[mt][nt], ah[mt], bl[nt]);
                }
        }
        __syncthreads();
    }

    const bool addb = (bias != nullptr) && (ks == 0);
    if (!out_half) {
        float* Cp = (float*)Cbase + (long)blockIdx.y * tile_stride + (long)ks * part_stride;
#pragma unroll
        for (int mt = 0; mt < 2; mt++) {
            int r = wm * 32 + mt * 16 + (lane >> 2);
#pragma unroll
            for (int nt = 0; nt < 4; nt++) {
                int col = n0 + wn * 32 + nt * 8 + (lane & 3) * 2;
                if (col < N) {
                    float bb = addb ? bias[col] : 0.f;
                    Cp[(long)r * row_stride + col]       = acc[mt][nt][0] + bb;
                    Cp[(long)(r + 8) * row_stride + col] = acc[mt][nt][2] + bb;
                }
                if (col + 1 < N) {
                    float bb = addb ? bias[col + 1] : 0.f;
                    Cp[(long)r * row_stride + col + 1]       = acc[mt][nt][1] + bb;
                    Cp[(long)(r + 8) * row_stride + col + 1] = acc[mt][nt][3] + bb;
                }
            }
        }
    } else {
        __half* Cp = (__half*)Cbase + (long)blockIdx.y * tile_stride + (long)ks * part_stride;
#pragma unroll
        for (int mt = 0; mt < 2; mt++) {
            int r = wm * 32 + mt * 16 + (lane >> 2);
#pragma unroll
            for (int nt = 0; nt < 4; nt++) {
                int col = n0 + wn * 32 + nt * 8 + (lane & 3) * 2;
                float b0 = addb ? bias[col] : 0.f;
                float b1 = addb ? bias[col + 1] : 0.f;
                __half2 w0 = {__float2half_rn(acc[mt][nt][0] + b0), __float2half_rn(acc[mt][nt][1] + b1)};
                __half2 w1 = {__float2half_rn(acc[mt][nt][2] + b0), __float2half_rn(acc[mt][nt][3] + b1)};
                *(__half2*)(Cp + (long)r * row_stride + col)       = w0;
                *(__half2*)(Cp + (long)(r + 8) * row_stride + col) = w1;
            }
        }
    }
}

// ---------------- fp16 1-MMA GEMM (single-B; att1 + preds) ------------------
static constexpr int S1A = 128 * 40;
static constexpr int S1B = 64 * 40;
static constexpr int S1TG = S1A + S1B;             // 7680 halves
static constexpr int GEMM1_SMEM = 2 * S1TG * 2;    // 30720 B

__global__ __launch_bounds__(256) void gemm1h(
    const __half* __restrict__ Ag, int lda,
    const __half* __restrict__ Bg, int ldb,
    const float* __restrict__ bias, void* __restrict__ Cbase,
    long tile_stride, long row_stride,
    int N, int Ktot, int out_half)
{
    extern __shared__ __align__(16) __half smh[];
    const int tid = threadIdx.x, lane = tid & 31, warp = tid >> 5;
    const int wm = warp >> 1, wn = warp & 1;
    const int n0 = blockIdx.x * 64, m0 = blockIdx.y * 128;

    float acc[2][4][4];
#pragma unroll
    for (int i = 0; i < 2; i++)
#pragma unroll
        for (int j = 0; j < 4; j++)
#pragma unroll
            for (int k = 0; k < 4; k++) acc[i][j][k] = 0.f;

    auto load_stage = [&](int st, int k0) {
        __half* As = smh + st * S1TG;
        __half* Bs = As + S1A;
#pragma unroll
        for (int it = 0; it < 2; it++) {
            int idx = tid + it * 256, r = idx >> 2, ch = idx & 3;
            CP16(s2u(As + r * 40 + ch * 8), Ag + (size_t)(m0 + r) * lda + k0 + ch * 8);
        }
        {
            int r = tid >> 2, ch = tid & 3;
            int rr = (n0 + r < N) ? (n0 + r) : (N - 1);
            CP16(s2u(Bs + r * 40 + ch * 8), Bg + (size_t)rr * ldb + k0 + ch * 8);
        }
        CPCOMMIT();
    };

    const int nk = Ktot / 32;
    load_stage(0, 0);
    for (int i = 0; i < nk; i++) {
        if (i + 1 < nk) {
            load_stage((i + 1) & 1, (i + 1) * 32);
            asm volatile("cp.async.wait_group 1;\n");
        } else {
            asm volatile("cp.async.wait_group 0;\n");
        }
        __syncthreads();
        __half* As = smh + (i & 1) * S1TG;
        __half* Bs = As + S1A;
#pragma unroll
        for (int kk = 0; kk < 32; kk += 16) {
            uint32_t ah[2][4], bh[4][2];
#pragma unroll
            for (int mt = 0; mt < 2; mt++) {
                int off = (wm * 32 + mt * 16 + (lane & 15)) * 40 + kk + ((lane >> 4) << 3);
                ldsm4(ah[mt], s2u(As + off));
            }
#pragma unroll
            for (int ng = 0; ng < 2; ng++) {
                int off = (wn * 32 + ng * 16 + (lane & 15)) * 40 + kk + ((lane >> 4) << 3);
                uint32_t t4[4];
                ldsm4(t4, s2u(Bs + off));
                bh[ng * 2][0] = t4[0]; bh[ng * 2][1] = t4[2];
                bh[ng * 2 + 1][0] = t4[1]; bh[ng * 2 + 1][1] = t4[3];
            }
#pragma unroll
            for (int mt = 0; mt < 2; mt++)
#pragma unroll
                for (int nt = 0; nt < 4; nt++)
                    mma16816h(acc[mt][nt], ah[mt], bh[nt]);
        }
        __syncthreads();
    }

    const bool addb = (bias != nullptr);
    if (!out_half) {
        float* Cp = (float*)Cbase + (long)blockIdx.y * tile_stride;
#pragma unroll
        for (int mt = 0; mt < 2; mt++) {
            int r = wm * 32 + mt * 16 + (lane >> 2);
#pragma unroll
            for (int nt = 0; nt < 4; nt++) {
                int col = n0 + wn * 32 + nt * 8 + (lane & 3) * 2;
                if (col < N) {
                    float bb = addb ? bias[col] : 0.f;
                    Cp[(long)r * row_stride + col]       = acc[mt][nt][0] + bb;
                    Cp[(long)(r + 8) * row_stride + col] = acc[mt][nt][2] + bb;
                }
                if (col + 1 < N) {
                    float bb = addb ? bias[col + 1] : 0.f;
                    Cp[(long)r * row_stride + col + 1]       = acc[mt][nt][1] + bb;
                    Cp[(long)(r + 8) * row_stride + col + 1] = acc[mt][nt][3] + bb;
                }
            }
        }
    } else {
        __half* Cp = (__half*)Cbase + (long)blockIdx.y * tile_stride;
#pragma unroll
        for (int mt = 0; mt < 2; mt++) {
            int r = wm * 32 + mt * 16 + (lane >> 2);
#pragma unroll
            for (int nt = 0; nt < 4; nt++) {
                int col = n0 + wn * 32 + nt * 8 + (lane & 3) * 2;
                float b0 = addb ? bias[col] : 0.f;
                float b1 = addb ? bias[col + 1] : 0.f;
                __half2 w0 = {__float2half_rn(acc[mt][nt][0] + b0), __float2half_rn(acc[mt][nt][1] + b1)};
                __half2 w1 = {__float2half_rn(acc[mt][nt][2] + b0), __float2half_rn(acc[mt][nt][3] + b1)};
                *(__half2*)(Cp + (long)r * row_stride + col)       = w0;
                *(__half2*)(Cp + (long)(r + 8) * row_stride + col) = w1;
            }
        }
    }
}

// ---------------- prep kernels ----------------------------------------------
__global__ void prep_img_k(const float* __restrict__ src, long n4)
{
    long i = (long)blockIdx.x * 256 + threadIdx.x;
    if (i >= n4) return;
    float4 v = ((const float4*)src)[i];
    ((__half2*)(g_img16 + 4 * i))[0] = {__float2half_rn(v.x), __float2half_rn(v.y)};
    ((__half2*)(g_img16 + 4 * i))[1] = {__float2half_rn(v.z), __float2half_rn(v.w)};
}

__global__ void tofp16_k(const float* __restrict__ src, __half* __restrict__ d, long n4)
{
    long i = (long)blockIdx.x * 256 + threadIdx.x;
    if (i >= n4) return;
    float4 v = ((const float4*)src)[i];
    ((__half2*)(d + 4 * i))[0] = {__float2half_rn(v.x), __float2half_rn(v.y)};
    ((__half2*)(d + 4 * i))[1] = {__float2half_rn(v.z), __float2half_rn(v.w)};
}

__global__ void split4h_k(const float* __restrict__ src, __half* __restrict__ dh,
                          __half* __restrict__ dl, long n4)
{
    long i = (long)blockIdx.x * 256 + threadIdx.x;
    if (i >= n4) return;
    float4 v = ((const float4*)src)[i];
    __half h0, h1, h2, h3, l0, l1, l2, l3;
    split2h(v.x, h0, l0); split2h(v.y, h1, l1); split2h(v.z, h2, l2); split2h(v.w, h3, l3);
    ((__half2*)(dh + 4 * i))[0] = {h0, h1};
    ((__half2*)(dh + 4 * i))[1] = {h2, h3};
    ((__half2*)(dl + 4 * i))[0] = {l0, l1};
    ((__half2*)(dl + 4 * i))[1] = {l2, l3};
}

__global__ void transpose_split_h(const float* __restrict__ src, __half* __restrict__ dh,
                                  __half* __restrict__ dl, int R, int C)
{
    __shared__ float tile[32][33];
    int c0 = blockIdx.x * 32, r0 = blockIdx.y * 32;
    int tx = threadIdx.x, ty = threadIdx.y;  // (32, 8)
#pragma unroll
    for (int i = 0; i < 4; i++) {
        int r = r0 + ty + i * 8;
        if (r < R && c0 + tx < C) tile[ty + i * 8][tx] = src[(size_t)r * C + c0 + tx];
    }
    __syncthreads();
#pragma unroll
    for (int i = 0; i < 4; i++) {
        int orow = c0 + ty + i * 8, ocol = r0 + tx;
        if (orow < C && ocol < R) {
            __half h, l;
            split2h(tile[tx][ty + i * 8], h, l);
            dh[(size_t)orow * R + ocol] = h;
            dl[(size_t)orow * R + ocol] = l;
        }
    }
}

__global__ void emb_gather_k(const float* __restrict__ emb, const int* __restrict__ cap)
{
    const int b = blockIdx.x, tt = blockIdx.y;   // tt = t-1, 0..18
    const int w = cap[b * 20 + tt];
    __half* dst = g_Xemb16 + (size_t)(tt * 128 + b) * 512;
    const float* s = emb + (size_t)w * 512;
    for (int i = threadIdx.x; i < 512; i += 128) dst[i] = __float2half_rn(s[i]);
}

__global__ void biascat_k(const float* __restrict__ bd, const float* __restrict__ bhh)
{
    int i = blockIdx.x * 256 + threadIdx.x;
    if (i < 512) g_bias_cat[i] = bd[i];
    else if (i < 2048) g_bias_cat[i] = bhh[i - 512];
}

__global__ void zero_h_k()
{
    int i = blockIdx.x * 256 + threadIdx.x;
    if (i < B_ * H_) { g_h[i] = 0.f; g_h16[i] = __float2half_rn(0.f); }
}

__global__ void init_out_k(float* __restrict__ out, const int* __restrict__ caplen)
{
    long i = (long)blockIdx.x * 256 + threadIdx.x;
    const long n0 = (long)B_ * V_;
    if (i < n0) {
        long b = i / V_, v2 = i % V_;
        out[b * 400000 + v2] = (v2 == 1) ? 1.f : 0.f;
    } else if (i < n0 + B_ * P_) {
        long j = i - n0, b = j / P_, p = j % P_;
        out[ALPHA_OFF + b * (T_ * P_) + p] = 0.f;
    } else if (i < n0 + B_ * P_ + B_) {
        int b = (int)(i - n0 - B_ * P_);
        out[CAP_OFF + b] = (float)caplen[b];
    }
}

// ---------------- per-step kernels ------------------------------------------
__global__ __launch_bounds__(256) void score_softmax_k(
    const float* __restrict__ wf, const float* __restrict__ bfp,
    float* __restrict__ out, int t)
{
    __shared__ float att2s[512], wfs[512], sc[200], red[256];
    const int b = blockIdx.x, tid = threadIdx.x, lane = tid & 31, warp = tid >> 5;
    for (int i = tid; i < 512; i += 256) {
        att2s[i] = g_ag[0][b * 2048 + i] + g_ag[1][b * 2048 + i];
        wfs[i] = wf[i];
    }
    __syncthreads();
    const float bfv = bfp[0];
    for (int p = warp; p < 196; p += 8) {
        const __half2* row = (const __half2*)(g_att1h + ((size_t)b * 196 + p) * 512);
        float s = 0.f;
#pragma unroll
        for (int i = 0; i < 8; i++) {
            int c = lane + i * 32;
            float2 vf = __half22float2(row[c]);
            s += fmaxf(vf.x + att2s[2 * c], 0.f) * wfs[2 * c]
               + fmaxf(vf.y + att2s[2 * c + 1], 0.f) * wfs[2 * c + 1];
        }
#pragma unroll
        for (int o = 16; o; o >>= 1) s += __shfl_xor_sync(0xffffffffu, s, o);
        if (lane == 0) sc[p] = s + bfv;
    }
    __syncthreads();
    float v = (tid < 196) ? sc[tid] : -1e30f;
    red[tid] = v; __syncthreads();
    for (int o = 128; o; o >>= 1) { if (tid < o) red[tid] = fmaxf(red[tid], red[tid + o]); __syncthreads(); }
    float m = red[0]; __syncthreads();
    float e = (tid < 196) ? __expf(sc[tid] - m) : 0.f;
    red[tid] = e; __syncthreads();
    for (int o = 128; o; o >>= 1) { if (tid < o) red[tid] += red[tid + o]; __syncthreads(); }
    float inv = 1.f / red[0];
    if (tid < 196) {
        float a = e * inv;
        g_alpha[b * 196 + tid] = a;
        out[ALPHA_OFF + ((size_t)b * 20 + t) * 196 + tid] = a;
    }
}

// ctx weighted sum (fp16 img, wide grid) -> x16 [128, 2048] fp16
__global__ void ctx_k()
{
    __shared__ float al[196];
    const int b = blockIdx.y, tid = threadIdx.x;
    for (int i = tid; i < 196; i += 128) al[i] = g_alpha[b * 196 + i];
    __syncthreads();
    const __half2* ip = (const __half2*)(g_img16 + (size_t)b * 196 * 2048);
    const int c0 = blockIdx.x * 256 + tid;   // half2 column, plus c0+128
    float2 a0 = {0.f, 0.f}, a1 = {0.f, 0.f};
#pragma unroll 4
    for (int p = 0; p < 196; p++) {
        const __half2* rp = ip + (size_t)p * 1024;
        float a = al[p];
        float2 v0 = __half22float2(rp[c0]);
        float2 v1 = __half22float2(rp[c0 + 128]);
        a0.x += a * v0.x; a0.y += a * v0.y;
        a1.x += a * v1.x; a1.y += a * v1.y;
    }
    *(__half2*)(g_x16 + b * 2048 + 2 * c0) =
        {__float2half_rn(a0.x), __float2half_rn(a0.y)};
    *(__half2*)(g_x16 + b * 2048 + 2 * (c0 + 128)) =
        {__float2half_rn(a1.x), __float2half_rn(a1.y)};
}

__global__ void gates_k(int t)
{
    int idx = blockIdx.x * 256 + threadIdx.x;
    if (idx >= B_ * H_) return;
    int b = idx >> 9, j = idx & 511;
    const float* ge = g_gi_emb + (size_t)((t - 1) * 128 + b) * 1536;
    int base = b * 1536;
    float gir = ge[j], giz = ge[512 + j], gin = ge[1024 + j];
#pragma unroll
    for (int s = 0; s < 4; s++) {
        gir += g_gi4[s][base + j];
        giz += g_gi4[s][base + 512 + j];
        gin += g_gi4[s][base + 1024 + j];
    }
    int gb = b * 2048;
    float ghr = g_ag[0][gb + 512 + j]  + g_ag[1][gb + 512 + j];
    float ghz = g_ag[0][gb + 1024 + j] + g_ag[1][gb + 1024 + j];
    float ghn = g_ag[0][gb + 1536 + j] + g_ag[1][gb + 1536 + j];
    float r = 1.f / (1.f + __expf(-(gir + ghr)));
    float z = 1.f / (1.f + __expf(-(giz + ghz)));
    float n = tanhf(gin + r * ghn);
    float h = g_h[idx];
    float hn = (1.f - z) * n + z * h;
    g_h[idx] = hn;
    __half h16 = __float2half_rn(hn);
    g_h16[idx] = h16;
    g_hall16[(t - 1) * (B_ * H_) + idx] = h16;
}

// ---------------- host -------------------------------------------------------
extern "C" void kernel_launch(void* const* d_in, const int* in_sizes, int n_in,
                              void* d_out, int out_size)
{
    const float* img = (const float*)d_in[0];
    const int*   cap = (const int*)d_in[1];
    const int*   cpl = (const int*)d_in[2];
    const float* emb = (const float*)d_in[3];
    const float* We  = (const float*)d_in[4];
    const float* be  = (const float*)d_in[5];
    const float* Wd  = (const float*)d_in[6];
    const float* bd  = (const float*)d_in[7];
    const float* Wf  = (const float*)d_in[8];
    const float* bfp = (const float*)d_in[9];
    const float* Wih = (const float*)d_in[10];
    const float* bih = (const float*)d_in[11];
    const float* Whh = (const float*)d_in[12];
    const float* bhh = (const float*)d_in[13];
    const float* Wo  = (const float*)d_in[14];
    const float* bo  = (const float*)d_in[15];
    float* out = (float*)d_out;

    static bool inited = false;
    if (!inited) {
        cudaFuncSetAttribute(gemm2h, cudaFuncAttributeMaxDynamicSharedMemorySize, GEMMH_SMEM);
        cudaFuncSetAttribute(gemm1h, cudaFuncAttributeMaxDynamicSharedMemorySize, GEMM1_SMEM);
        inited = true;
    }

    void *pImg16, *pAtt1h, *pWe16h, *pWe16l, *pBc16h, *pBc16l, *pBias;
    void *pWih16h, *pWih16l, *pWo16, *pXe16, *pGiE, *pAg, *pGi4, *pX16, *pH16, *pHa16;
    cudaGetSymbolAddress(&pImg16, g_img16);
    cudaGetSymbolAddress(&pAtt1h, g_att1h);
    cudaGetSymbolAddress(&pWe16h, g_WeT16h);  cudaGetSymbolAddress(&pWe16l, g_WeT16l);
    cudaGetSymbolAddress(&pBc16h, g_Bcat16h); cudaGetSymbolAddress(&pBc16l, g_Bcat16l);
    cudaGetSymbolAddress(&pBias, g_bias_cat);
    cudaGetSymbolAddress(&pWih16h, g_Wih16h); cudaGetSymbolAddress(&pWih16l, g_Wih16l);
    cudaGetSymbolAddress(&pWo16, g_Wo16);
    cudaGetSymbolAddress(&pXe16, g_Xemb16);   cudaGetSymbolAddress(&pGiE, g_gi_emb);
    cudaGetSymbolAddress(&pAg, g_ag);         cudaGetSymbolAddress(&pGi4, g_gi4);
    cudaGetSymbolAddress(&pX16, g_x16);       cudaGetSymbolAddress(&pH16, g_h16);
    cudaGetSymbolAddress(&pHa16, g_hall16);

    // ---- prep ----
    {
        long n4 = (long)M1_ * ENC_ / 4;
        prep_img_k<<<(int)((n4 + 255) / 256), 256>>>(img, n4);
    }
    transpose_split_h<<<dim3(16, 64), dim3(32, 8)>>>(We, (__half*)pWe16h, (__half*)pWe16l, 2048, 512);
    transpose_split_h<<<dim3(16, 16), dim3(32, 8)>>>(Wd, (__half*)pBc16h, (__half*)pBc16l, 512, 512);
    {
        long n4 = (long)H3_ * H_ / 4;
        split4h_k<<<(int)((n4 + 255) / 256), 256>>>(Whh, (__half*)pBc16h + 512 * 512, (__half*)pBc16l + 512 * 512, n4);
    }
    {
        long n4 = (long)H3_ * EX_ / 4;
        split4h_k<<<(int)((n4 + 255) / 256), 256>>>(Wih, (__half*)pWih16h, (__half*)pWih16l, n4);
    }
    {
        long n4 = (long)V_ * H_ / 4;
        tofp16_k<<<(int)((n4 + 255) / 256), 256>>>(Wo, (__half*)pWo16, n4);
    }
    emb_gather_k<<<dim3(128, 19), 128>>>(emb, cap);
    biascat_k<<<8, 256>>>(bd, bhh);
    zero_h_k<<<256, 256>>>();
    {
        long tot = (long)B_ * V_ + B_ * P_ + B_;
        init_out_k<<<(int)((tot + 255) / 256), 256>>>(out, cpl);
    }

    // att1 = img16 @ WeT16^T + be -> fp16 [25088, 512]  (single-B, 1-MMA)
    gemm1h<<<dim3(8, 196), 256, GEMM1_SMEM>>>(
        (const __half*)pImg16, 2048, (const __half*)pWe16h, 2048,
        be, pAtt1h, (long)128 * 512, 512, 512, 2048, 1);

    // gi_emb = Xemb @ Wih[:, :512]^T + bih -> [2432, 1536] fp32 (2-MMA)
    gemm2h<<<dim3(24, 19, 1), 256, GEMMH_SMEM>>>(
        (const __half*)pXe16, 512, (const __half*)pWih16h, (const __half*)pWih16l, 2560,
        bih, pGiE, (long)128 * 1536, 1536, 0, 1536, 512, 0);

    for (int t = 1; t < 20; t++) {
        // [att2 | gh] = h16 @ Bcat16^T (+biascat), split-K=2 -> g_ag[0],g_ag[1]
        gemm2h<<<dim3(32, 1, 2), 256, GEMMH_SMEM>>>(
            (const __half*)pH16, 512, (const __half*)pBc16h, (const __half*)pBc16l, 512,
            (const float*)pBias, pAg, 0, 2048, (long)B_ * 2048, 2048, 512, 0);
        score_softmax_k<<<128, 256>>>(Wf, bfp, out, t);
        ctx_k<<<dim3(4, 128), 128>>>();
        // gi_ctx = x16 @ Wih[:, 512:]^T, split-K=4 -> g_gi4[0..3]
        gemm2h<<<dim3(24, 1, 4), 256, GEMMH_SMEM>>>(
            (const __half*)pX16, 2048, (const __half*)pWih16h + 512, (const __half*)pWih16l + 512, 2560,
            nullptr, pGi4, 0, 1536, (long)B_ * 1536, 1536, 2048, 0);
        gates_k<<<256, 256>>>(t);
    }

    // preds (batched, single-B): [2432, 20000] -> out[b*400000 + t*20000 + v]
    gemm1h<<<dim3(313, 19), 256, GEMM1_SMEM>>>(
        (const __half*)pHa16, 512, (const __half*)pWo16, 512,
        bo, out + 20000, 20000, 400000, 20000, 512, 0);

    (void)in_sizes; (void)n_in; (void)out_size;
}

// round 15
// speedup vs baseline: 1.2938x; 1.0319x over previous
#include <cuda_runtime.h>
#include <cuda_bf16.h>
#include <cuda_fp16.h>
#include <cstdint>

static constexpr int B_ = 128, P_ = 196, ENC_ = 2048, A_ = 512, H_ = 512;
static constexpr int V_ = 20000, T_ = 20, H3_ = 1536, EX_ = 2560;
static constexpr long CAP_OFF   = (long)B_ * T_ * V_;   // 51,200,000
static constexpr long ALPHA_OFF = CAP_OFF + B_;         // 51,200,128
static constexpr int  M1_ = B_ * P_;                    // 25088
static constexpr int  MH_ = (T_ - 1) * B_;              // 2432

// ---------------- device scratch ------------------------------------------
__device__ __align__(16) __half g_img16[(size_t)M1_ * ENC_];
__device__ __align__(16) __half g_att1h[(size_t)M1_ * A_];
__device__ __align__(16) __half g_WeT16[A_ * ENC_];
__device__ __align__(16) __half g_Bcat16[2048 * 512];
__device__ __align__(16) float  g_bias_cat[2048];
__device__ __align__(16) __half g_Wih16[H3_ * EX_];
__device__ __align__(16) __half g_Wo16[(size_t)V_ * H_];
__device__ __align__(16) __half g_Xemb16[MH_ * 512];
__device__ __align__(16) float  g_gi_emb[(size_t)MH_ * H3_];
__device__ __align__(16) float  g_ag[2][B_ * 2048];     // split-K partials: att2|gh
__device__ __align__(16) float  g_gi4[4][B_ * H3_];     // split-K partials: gi_ctx
__device__ __align__(16) float  g_alpha[B_ * P_];
__device__ __align__(16) __half g_x16[B_ * ENC_];       // ctx fp16
__device__ __align__(16) float  g_h[B_ * H_];
__device__ __align__(16) __half g_h16[B_ * H_];
__device__ __align__(16) __half g_hall16[MH_ * H_];

// ---------------- helpers --------------------------------------------------
__device__ __forceinline__ uint32_t s2u(const void* p) {
    return (uint32_t)__cvta_generic_to_shared(p);
}
__device__ __forceinline__ void ldsm4(uint32_t r[4], uint32_t a) {
    asm volatile("ldmatrix.sync.aligned.m8n8.x4.shared.b16 {%0,%1,%2,%3},[%4];"
                 : "=r"(r[0]), "=r"(r[1]), "=r"(r[2]), "=r"(r[3]) : "r"(a));
}
__device__ __forceinline__ void mma16816h(float c[4], const uint32_t a[4], const uint32_t b[2]) {
    asm volatile(
        "mma.sync.aligned.m16n8k16.row.col.f32.f16.f16.f32 "
        "{%0,%1,%2,%3},{%4,%5,%6,%7},{%8,%9},{%0,%1,%2,%3};"
        : "+f"(c[0]), "+f"(c[1]), "+f"(c[2]), "+f"(c[3])
        : "r"(a[0]), "r"(a[1]), "r"(a[2]), "r"(a[3]), "r"(b[0]), "r"(b[1]));
}
#define CP16(d, s) asm volatile("cp.async.cg.shared.global [%0],[%1],16;\n" :: "r"(d), "l"(s))
#define CPCOMMIT() asm volatile("cp.async.commit_group;\n")

// ---------------- fp16 1-MMA GEMM (single-B, split-K capable) ----------------
// A [M,K] fp16 row-major. B [N,K] fp16 row-major.
// 256 thr, tile 128x64x32, cp.async double-buffered, 80B-padded smem rows.
// blockIdx.z = split-K slice; partial at Cbase + z*part_stride (bias on z==0).
static constexpr int S1A = 128 * 40;
static constexpr int S1B = 64 * 40;
static constexpr int S1TG = S1A + S1B;             // 7680 halves
static constexpr int GEMM1_SMEM = 2 * S1TG * 2;    // 30720 B

__global__ __launch_bounds__(256) void gemm1h(
    const __half* __restrict__ Ag, int lda,
    const __half* __restrict__ Bg, int ldb,
    const float* __restrict__ bias, void* __restrict__ Cbase,
    long tile_stride, long row_stride, long part_stride,
    int N, int Ktot, int out_half)
{
    extern __shared__ __align__(16) __half smh[];
    const int tid = threadIdx.x, lane = tid & 31, warp = tid >> 5;
    const int wm = warp >> 1, wn = warp & 1;
    const int n0 = blockIdx.x * 64, m0 = blockIdx.y * 128;
    const int ks = blockIdx.z;
    const int Ksub = Ktot / gridDim.z, kbase = ks * Ksub;

    float acc[2][4][4];
#pragma unroll
    for (int i = 0; i < 2; i++)
#pragma unroll
        for (int j = 0; j < 4; j++)
#pragma unroll
            for (int k = 0; k < 4; k++) acc[i][j][k] = 0.f;

    auto load_stage = [&](int st, int k0) {
        __half* As = smh + st * S1TG;
        __half* Bs = As + S1A;
#pragma unroll
        for (int it = 0; it < 2; it++) {
            int idx = tid + it * 256, r = idx >> 2, ch = idx & 3;
            CP16(s2u(As + r * 40 + ch * 8), Ag + (size_t)(m0 + r) * lda + kbase + k0 + ch * 8);
        }
        {
            int r = tid >> 2, ch = tid & 3;
            int rr = (n0 + r < N) ? (n0 + r) : (N - 1);
            CP16(s2u(Bs + r * 40 + ch * 8), Bg + (size_t)rr * ldb + kbase + k0 + ch * 8);
        }
        CPCOMMIT();
    };

    const int nk = Ksub / 32;
    load_stage(0, 0);
    for (int i = 0; i < nk; i++) {
        if (i + 1 < nk) {
            load_stage((i + 1) & 1, (i + 1) * 32);
            asm volatile("cp.async.wait_group 1;\n");
        } else {
            asm volatile("cp.async.wait_group 0;\n");
        }
        __syncthreads();
        __half* As = smh + (i & 1) * S1TG;
        __half* Bs = As + S1A;
#pragma unroll
        for (int kk = 0; kk < 32; kk += 16) {
            uint32_t ah[2][4], bh[4][2];
#pragma unroll
            for (int mt = 0; mt < 2; mt++) {
                int off = (wm * 32 + mt * 16 + (lane & 15)) * 40 + kk + ((lane >> 4) << 3);
                ldsm4(ah[mt], s2u(As + off));
            }
#pragma unroll
            for (int ng = 0; ng < 2; ng++) {
                int off = (wn * 32 + ng * 16 + (lane & 15)) * 40 + kk + ((lane >> 4) << 3);
                uint32_t t4[4];
                ldsm4(t4, s2u(Bs + off));
                bh[ng * 2][0] = t4[0]; bh[ng * 2][1] = t4[2];
                bh[ng * 2 + 1][0] = t4[1]; bh[ng * 2 + 1][1] = t4[3];
            }
#pragma unroll
            for (int mt = 0; mt < 2; mt++)
#pragma unroll
                for (int nt = 0; nt < 4; nt++)
                    mma16816h(acc[mt][nt], ah[mt], bh[nt]);
        }
        __syncthreads();
    }

    const bool addb = (bias != nullptr) && (ks == 0);
    if (!out_half) {
        float* Cp = (float*)Cbase + (long)blockIdx.y * tile_stride + (long)ks * part_stride;
#pragma unroll
        for (int mt = 0; mt < 2; mt++) {
            int r = wm * 32 + mt * 16 + (lane >> 2);
#pragma unroll
            for (int nt = 0; nt < 4; nt++) {
                int col = n0 + wn * 32 + nt * 8 + (lane & 3) * 2;
                if (col < N) {
                    float bb = addb ? bias[col] : 0.f;
                    Cp[(long)r * row_stride + col]       = acc[mt][nt][0] + bb;
                    Cp[(long)(r + 8) * row_stride + col] = acc[mt][nt][2] + bb;
                }
                if (col + 1 < N) {
                    float bb = addb ? bias[col + 1] : 0.f;
                    Cp[(long)r * row_stride + col + 1]       = acc[mt][nt][1] + bb;
                    Cp[(long)(r + 8) * row_stride + col + 1] = acc[mt][nt][3] + bb;
                }
            }
        }
    } else {
        __half* Cp = (__half*)Cbase + (long)blockIdx.y * tile_stride + (long)ks * part_stride;
#pragma unroll
        for (int mt = 0; mt < 2; mt++) {
            int r = wm * 32 + mt * 16 + (lane >> 2);
#pragma unroll
            for (int nt = 0; nt < 4; nt++) {
                int col = n0 + wn * 32 + nt * 8 + (lane & 3) * 2;
                float b0 = addb ? bias[col] : 0.f;
                float b1 = addb ? bias[col + 1] : 0.f;
                __half2 w0 = {__float2half_rn(acc[mt][nt][0] + b0), __float2half_rn(acc[mt][nt][1] + b1)};
                __half2 w1 = {__float2half_rn(acc[mt][nt][2] + b0), __float2half_rn(acc[mt][nt][3] + b1)};
                *(__half2*)(Cp + (long)r * row_stride + col)       = w0;
                *(__half2*)(Cp + (long)(r + 8) * row_stride + col) = w1;
            }
        }
    }
}

// ---------------- prep kernels ----------------------------------------------
__global__ void prep_img_k(const float* __restrict__ src, long n4)
{
    long i = (long)blockIdx.x * 256 + threadIdx.x;
    if (i >= n4) return;
    float4 v = ((const float4*)src)[i];
    ((__half2*)(g_img16 + 4 * i))[0] = {__float2half_rn(v.x), __float2half_rn(v.y)};
    ((__half2*)(g_img16 + 4 * i))[1] = {__float2half_rn(v.z), __float2half_rn(v.w)};
}

__global__ void tofp16_k(const float* __restrict__ src, __half* __restrict__ d, long n4)
{
    long i = (long)blockIdx.x * 256 + threadIdx.x;
    if (i >= n4) return;
    float4 v = ((const float4*)src)[i];
    ((__half2*)(d + 4 * i))[0] = {__float2half_rn(v.x), __float2half_rn(v.y)};
    ((__half2*)(d + 4 * i))[1] = {__float2half_rn(v.z), __float2half_rn(v.w)};
}

__global__ void transpose_h(const float* __restrict__ src, __half* __restrict__ d,
                            int R, int C)
{
    __shared__ float tile[32][33];
    int c0 = blockIdx.x * 32, r0 = blockIdx.y * 32;
    int tx = threadIdx.x, ty = threadIdx.y;  // (32, 8)
#pragma unroll
    for (int i = 0; i < 4; i++) {
        int r = r0 + ty + i * 8;
        if (r < R && c0 + tx < C) tile[ty + i * 8][tx] = src[(size_t)r * C + c0 + tx];
    }
    __syncthreads();
#pragma unroll
    for (int i = 0; i < 4; i++) {
        int orow = c0 + ty + i * 8, ocol = r0 + tx;
        if (orow < C && ocol < R)
            d[(size_t)orow * R + ocol] = __float2half_rn(tile[tx][ty + i * 8]);
    }
}

__global__ void emb_gather_k(const float* __restrict__ emb, const int* __restrict__ cap)
{
    const int b = blockIdx.x, tt = blockIdx.y;   // tt = t-1, 0..18
    const int w = cap[b * 20 + tt];
    __half* dst = g_Xemb16 + (size_t)(tt * 128 + b) * 512;
    const float* s = emb + (size_t)w * 512;
    for (int i = threadIdx.x; i < 512; i += 128) dst[i] = __float2half_rn(s[i]);
}

__global__ void biascat_k(const float* __restrict__ bd, const float* __restrict__ bhh)
{
    int i = blockIdx.x * 256 + threadIdx.x;
    if (i < 512) g_bias_cat[i] = bd[i];
    else if (i < 2048) g_bias_cat[i] = bhh[i - 512];
}

__global__ void zero_h_k()
{
    int i = blockIdx.x * 256 + threadIdx.x;
    if (i < B_ * H_) { g_h[i] = 0.f; g_h16[i] = __float2half_rn(0.f); }
}

__global__ void init_out_k(float* __restrict__ out, const int* __restrict__ caplen)
{
    long i = (long)blockIdx.x * 256 + threadIdx.x;
    const long n0 = (long)B_ * V_;
    if (i < n0) {
        long b = i / V_, v2 = i % V_;
        out[b * 400000 + v2] = (v2 == 1) ? 1.f : 0.f;
    } else if (i < n0 + B_ * P_) {
        long j = i - n0, b = j / P_, p = j % P_;
        out[ALPHA_OFF + b * (T_ * P_) + p] = 0.f;
    } else if (i < n0 + B_ * P_ + B_) {
        int b = (int)(i - n0 - B_ * P_);
        out[CAP_OFF + b] = (float)caplen[b];
    }
}

// ---------------- per-step kernels ------------------------------------------
__global__ __launch_bounds__(256) void score_softmax_k(
    const float* __restrict__ wf, const float* __restrict__ bfp,
    float* __restrict__ out, int t)
{
    __shared__ float att2s[512], wfs[512], sc[200], red[256];
    const int b = blockIdx.x, tid = threadIdx.x, lane = tid & 31, warp = tid >> 5;
    for (int i = tid; i < 512; i += 256) {
        att2s[i] = g_ag[0][b * 2048 + i] + g_ag[1][b * 2048 + i];
        wfs[i] = wf[i];
    }
    __syncthreads();
    const float bfv = bfp[0];
    for (int p = warp; p < 196; p += 8) {
        const __half2* row = (const __half2*)(g_att1h + ((size_t)b * 196 + p) * 512);
        float s = 0.f;
#pragma unroll
        for (int i = 0; i < 8; i++) {
            int c = lane + i * 32;
            float2 vf = __half22float2(row[c]);
            s += fmaxf(vf.x + att2s[2 * c], 0.f) * wfs[2 * c]
               + fmaxf(vf.y + att2s[2 * c + 1], 0.f) * wfs[2 * c + 1];
        }
#pragma unroll
        for (int o = 16; o; o >>= 1) s += __shfl_xor_sync(0xffffffffu, s, o);
        if (lane == 0) sc[p] = s + bfv;
    }
    __syncthreads();
    float v = (tid < 196) ? sc[tid] : -1e30f;
    red[tid] = v; __syncthreads();
    for (int o = 128; o; o >>= 1) { if (tid < o) red[tid] = fmaxf(red[tid], red[tid + o]); __syncthreads(); }
    float m = red[0]; __syncthreads();
    float e = (tid < 196) ? __expf(sc[tid] - m) : 0.f;
    red[tid] = e; __syncthreads();
    for (int o = 128; o; o >>= 1) { if (tid < o) red[tid] += red[tid + o]; __syncthreads(); }
    float inv = 1.f / red[0];
    if (tid < 196) {
        float a = e * inv;
        g_alpha[b * 196 + tid] = a;
        out[ALPHA_OFF + ((size_t)b * 20 + t) * 196 + tid] = a;
    }
}

// ctx weighted sum (fp16 img, wide grid) -> x16 [128, 2048] fp16
__global__ void ctx_k()
{
    __shared__ float al[196];
    const int b = blockIdx.y, tid = threadIdx.x;
    for (int i = tid; i < 196; i += 128) al[i] = g_alpha[b * 196 + i];
    __syncthreads();
    const __half2* ip = (const __half2*)(g_img16 + (size_t)b * 196 * 2048);
    const int c0 = blockIdx.x * 256 + tid;   // half2 column, plus c0+128
    float2 a0 = {0.f, 0.f}, a1 = {0.f, 0.f};
#pragma unroll 4
    for (int p = 0; p < 196; p++) {
        const __half2* rp = ip + (size_t)p * 1024;
        float a = al[p];
        float2 v0 = __half22float2(rp[c0]);
        float2 v1 = __half22float2(rp[c0 + 128]);
        a0.x += a * v0.x; a0.y += a * v0.y;
        a1.x += a * v1.x; a1.y += a * v1.y;
    }
    *(__half2*)(g_x16 + b * 2048 + 2 * c0) =
        {__float2half_rn(a0.x), __float2half_rn(a0.y)};
    *(__half2*)(g_x16 + b * 2048 + 2 * (c0 + 128)) =
        {__float2half_rn(a1.x), __float2half_rn(a1.y)};
}

__global__ void gates_k(int t)
{
    int idx = blockIdx.x * 256 + threadIdx.x;
    if (idx >= B_ * H_) return;
    int b = idx >> 9, j = idx & 511;
    const float* ge = g_gi_emb + (size_t)((t - 1) * 128 + b) * 1536;
    int base = b * 1536;
    float gir = ge[j], giz = ge[512 + j], gin = ge[1024 + j];
#pragma unroll
    for (int s = 0; s < 4; s++) {
        gir += g_gi4[s][base + j];
        giz += g_gi4[s][base + 512 + j];
        gin += g_gi4[s][base + 1024 + j];
    }
    int gb = b * 2048;
    float ghr = g_ag[0][gb + 512 + j]  + g_ag[1][gb + 512 + j];
    float ghz = g_ag[0][gb + 1024 + j] + g_ag[1][gb + 1024 + j];
    float ghn = g_ag[0][gb + 1536 + j] + g_ag[1][gb + 1536 + j];
    float r = 1.f / (1.f + __expf(-(gir + ghr)));
    float z = 1.f / (1.f + __expf(-(giz + ghz)));
    float n = tanhf(gin + r * ghn);
    float h = g_h[idx];
    float hn = (1.f - z) * n + z * h;
    g_h[idx] = hn;
    __half h16 = __float2half_rn(hn);
    g_h16[idx] = h16;
    g_hall16[(t - 1) * (B_ * H_) + idx] = h16;
}

// ---------------- host -------------------------------------------------------
extern "C" void kernel_launch(void* const* d_in, const int* in_sizes, int n_in,
                              void* d_out, int out_size)
{
    const float* img = (const float*)d_in[0];
    const int*   cap = (const int*)d_in[1];
    const int*   cpl = (const int*)d_in[2];
    const float* emb = (const float*)d_in[3];
    const float* We  = (const float*)d_in[4];
    const float* be  = (const float*)d_in[5];
    const float* Wd  = (const float*)d_in[6];
    const float* bd  = (const float*)d_in[7];
    const float* Wf  = (const float*)d_in[8];
    const float* bfp = (const float*)d_in[9];
    const float* Wih = (const float*)d_in[10];
    const float* bih = (const float*)d_in[11];
    const float* Whh = (const float*)d_in[12];
    const float* bhh = (const float*)d_in[13];
    const float* Wo  = (const float*)d_in[14];
    const float* bo  = (const float*)d_in[15];
    float* out = (float*)d_out;

    static bool inited = false;
    if (!inited) {
        cudaFuncSetAttribute(gemm1h, cudaFuncAttributeMaxDynamicSharedMemorySize, GEMM1_SMEM);
        inited = true;
    }

    void *pImg16, *pAtt1h, *pWe16, *pBc16, *pBias;
    void *pWih16, *pWo16, *pXe16, *pGiE, *pAg, *pGi4, *pX16, *pH16, *pHa16;
    cudaGetSymbolAddress(&pImg16, g_img16);
    cudaGetSymbolAddress(&pAtt1h, g_att1h);
    cudaGetSymbolAddress(&pWe16, g_WeT16);
    cudaGetSymbolAddress(&pBc16, g_Bcat16);
    cudaGetSymbolAddress(&pBias, g_bias_cat);
    cudaGetSymbolAddress(&pWih16, g_Wih16);
    cudaGetSymbolAddress(&pWo16, g_Wo16);
    cudaGetSymbolAddress(&pXe16, g_Xemb16);   cudaGetSymbolAddress(&pGiE, g_gi_emb);
    cudaGetSymbolAddress(&pAg, g_ag);         cudaGetSymbolAddress(&pGi4, g_gi4);
    cudaGetSymbolAddress(&pX16, g_x16);       cudaGetSymbolAddress(&pH16, g_h16);
    cudaGetSymbolAddress(&pHa16, g_hall16);

    // ---- prep ----
    {
        long n4 = (long)M1_ * ENC_ / 4;
        prep_img_k<<<(int)((n4 + 255) / 256), 256>>>(img, n4);
    }
    transpose_h<<<dim3(16, 64), dim3(32, 8)>>>(We, (__half*)pWe16, 2048, 512);
    transpose_h<<<dim3(16, 16), dim3(32, 8)>>>(Wd, (__half*)pBc16, 512, 512);
    {
        long n4 = (long)H3_ * H_ / 4;
        tofp16_k<<<(int)((n4 + 255) / 256), 256>>>(Whh, (__half*)pBc16 + 512 * 512, n4);
    }
    {
        long n4 = (long)H3_ * EX_ / 4;
        tofp16_k<<<(int)((n4 + 255) / 256), 256>>>(Wih, (__half*)pWih16, n4);
    }
    {
        long n4 = (long)V_ * H_ / 4;
        tofp16_k<<<(int)((n4 + 255) / 256), 256>>>(Wo, (__half*)pWo16, n4);
    }
    emb_gather_k<<<dim3(128, 19), 128>>>(emb, cap);
    biascat_k<<<8, 256>>>(bd, bhh);
    zero_h_k<<<256, 256>>>();
    {
        long tot = (long)B_ * V_ + B_ * P_ + B_;
        init_out_k<<<(int)((tot + 255) / 256), 256>>>(out, cpl);
    }

    // att1 = img16 @ WeT16^T + be -> fp16 [25088, 512]
    gemm1h<<<dim3(8, 196, 1), 256, GEMM1_SMEM>>>(
        (const __half*)pImg16, 2048, (const __half*)pWe16, 2048,
        be, pAtt1h, (long)128 * 512, 512, 0, 512, 2048, 1);

    // gi_emb = Xemb @ Wih[:, :512]^T + bih -> [2432, 1536] fp32
    gemm1h<<<dim3(24, 19, 1), 256, GEMM1_SMEM>>>(
        (const __half*)pXe16, 512, (const __half*)pWih16, 2560,
        bih, pGiE, (long)128 * 1536, 1536, 0, 1536, 512, 0);

    for (int t = 1; t < 20; t++) {
        // [att2 | gh] = h16 @ Bcat16^T (+biascat), split-K=2 -> g_ag[0],g_ag[1]
        gemm1h<<<dim3(32, 1, 2), 256, GEMM1_SMEM>>>(
            (const __half*)pH16, 512, (const __half*)pBc16, 512,
            (const float*)pBias, pAg, 0, 2048, (long)B_ * 2048, 2048, 512, 0);
        score_softmax_k<<<128, 256>>>(Wf, bfp, out, t);
        ctx_k<<<dim3(4, 128), 128>>>();
        // gi_ctx = x16 @ Wih[:, 512:]^T, split-K=4 -> g_gi4[0..3]
        gemm1h<<<dim3(24, 1, 4), 256, GEMM1_SMEM>>>(
            (const __half*)pX16, 2048, (const __half*)pWih16 + 512, 2560,
            nullptr, pGi4, 0, 1536, (long)B_ * 1536, 1536, 2048, 0);
        gates_k<<<256, 256>>>(t);
    }

    // preds (batched): [2432, 20000] -> out[b*400000 + t*20000 + v]
    gemm1h<<<dim3(313, 19, 1), 256, GEMM1_SMEM>>>(
        (const __half*)pHa16, 512, (const __half*)pWo16, 512,
        bo, out + 20000, 20000, 400000, 0, 20000, 512, 0);

    (void)in_sizes; (void)n_in; (void)out_size;
}